// round 1
// baseline (speedup 1.0000x reference)
#include <cuda_runtime.h>

#define N_NODES 100000
#define N_EDGES 3200000
#define D 64
#define H 4096
#define TH 12288  // 3*H

// -------- device scratch (no allocations allowed) --------
__device__ float g_deg[2 * N_NODES];          // [out_deg | in_deg]
__device__ float g_outnorm[N_NODES];
__device__ float g_innorm[N_NODES];
__device__ float g_gi[2][TH];                 // W_ih @ x + b_ih, per cell
__device__ float g_gh[2][TH];                 // W_hh @ h + b_hh, per cell
__device__ float g_w[2][H];                   // evolved weights w1, w2 (flat)
__device__ float g_xs[(size_t)N_NODES * D];   // current layer input, pre-scaled by out_norm
__device__ float g_agg[(size_t)N_NODES * D];  // segment-sum accumulator

// -------- degrees --------
__global__ void k_degree(const int* __restrict__ src, const int* __restrict__ dst) {
    int e = blockIdx.x * blockDim.x + threadIdx.x;
    if (e >= N_EDGES) return;
    atomicAdd(&g_deg[src[e]], 1.0f);
    atomicAdd(&g_deg[N_NODES + dst[e]], 1.0f);
}

__global__ void k_norms() {
    int i = blockIdx.x * blockDim.x + threadIdx.x;
    if (i >= N_NODES) return;
    g_outnorm[i] = rsqrtf(fmaxf(g_deg[i], 1.0f));
    g_innorm[i]  = rsqrtf(fmaxf(g_deg[N_NODES + i], 1.0f));
}

// -------- pre-scale layer-1 input by out_norm --------
__global__ void k_scale_in(const float* __restrict__ x) {
    int t = blockIdx.x * blockDim.x + threadIdx.x;
    if (t >= N_NODES * 16) return;
    int row = t >> 4;
    float4 v = ((const float4*)x)[t];
    float s = g_outnorm[row];
    v.x *= s; v.y *= s; v.z *= s; v.w *= s;
    ((float4*)g_xs)[t] = v;
}

// -------- GRU matvec: each warp = one weight row, dotted against BOTH cells' vectors --------
// blocks [0,1536): W_ih vs (prev_gc1, prev_gc2)   -> g_gi
// blocks [1536,3072): W_hh vs (gc1_flat, gc2_flat) -> g_gh
__global__ void k_gru_mv(const float* __restrict__ W_ih, const float* __restrict__ W_hh,
                         const float* __restrict__ b_ih, const float* __restrict__ b_hh,
                         const float* __restrict__ x1, const float* __restrict__ x2,
                         const float* __restrict__ h1, const float* __restrict__ h2) {
    __shared__ float4 sv1[H / 4];
    __shared__ float4 sv2[H / 4];
    const int HB = TH / 8;  // 1536 blocks per matrix (8 warps/block)
    bool hh = blockIdx.x >= HB;
    const float* W  = hh ? W_hh : W_ih;
    const float* b  = hh ? b_hh : b_ih;
    const float* v1 = hh ? h1 : x1;
    const float* v2 = hh ? h2 : x2;
    float* o1 = hh ? g_gh[0] : g_gi[0];
    float* o2 = hh ? g_gh[1] : g_gi[1];

    for (int i = threadIdx.x; i < H / 4; i += blockDim.x) {
        sv1[i] = ((const float4*)v1)[i];
        sv2[i] = ((const float4*)v2)[i];
    }
    __syncthreads();

    int warp = threadIdx.x >> 5, lane = threadIdx.x & 31;
    int row = (blockIdx.x % HB) * 8 + warp;
    const float4* wr = (const float4*)(W + (size_t)row * H);
    float a1 = 0.0f, a2 = 0.0f;
#pragma unroll 4
    for (int k = lane; k < H / 4; k += 32) {
        float4 w = wr[k];
        float4 p = sv1[k];
        float4 q = sv2[k];
        a1 += w.x * p.x + w.y * p.y + w.z * p.z + w.w * p.w;
        a2 += w.x * q.x + w.y * q.y + w.z * q.z + w.w * q.w;
    }
#pragma unroll
    for (int o = 16; o; o >>= 1) {
        a1 += __shfl_xor_sync(0xffffffffu, a1, o);
        a2 += __shfl_xor_sync(0xffffffffu, a2, o);
    }
    if (lane == 0) {
        float bb = b[row];
        o1[row] = a1 + bb;
        o2[row] = a2 + bb;
    }
}

__device__ __forceinline__ float sigm(float x) { return 1.0f / (1.0f + expf(-x)); }

// -------- GRU gate combine -> evolved weights --------
__global__ void k_gru_combine(const float* __restrict__ gc1w, const float* __restrict__ gc2w) {
    int j = blockIdx.x * blockDim.x + threadIdx.x;
    int c = blockIdx.y;
    if (j >= H) return;
    const float* gi = g_gi[c];
    const float* gh = g_gh[c];
    const float* hv = c ? gc2w : gc1w;  // hidden state = current (flattened) gc weight
    float r = sigm(gi[j] + gh[j]);
    float z = sigm(gi[H + j] + gh[H + j]);
    float n = tanhf(gi[2 * H + j] + r * gh[2 * H + j]);
    g_w[c][j] = (1.0f - z) * n + z * hv[j];
}

// -------- edge gather + scatter-reduce (pure: input already out_norm-scaled) --------
__global__ void k_edge(const int* __restrict__ src, const int* __restrict__ dst) {
    int t = blockIdx.x * blockDim.x + threadIdx.x;
    if (t >= N_EDGES * 16) return;
    int e = t >> 4;
    int c = t & 15;
    int s = __ldg(src + e);
    int d = __ldg(dst + e);
    float4 v = ((const float4*)g_xs)[(size_t)s * 16 + c];
    float* p = g_agg + ((size_t)d * D + c * 4);
    asm volatile("red.global.add.v4.f32 [%0], {%1, %2, %3, %4};"
                 :: "l"(p), "f"(v.x), "f"(v.y), "f"(v.z), "f"(v.w) : "memory");
}

// -------- per-node transform: out = act((agg * in_norm) @ W + b) [* out_norm] --------
template <bool RELU, bool OUTSCALE>
__global__ void k_transform(const float* __restrict__ Wm, const float* __restrict__ bias,
                            float* __restrict__ out) {
    __shared__ float sW[D * D];
    __shared__ float sb[D];
    __shared__ float srow[8][D];
    for (int i = threadIdx.x; i < D * D; i += blockDim.x) sW[i] = Wm[i];
    if (threadIdx.x < D) sb[threadIdx.x] = bias[threadIdx.x];
    __syncthreads();

    int warp = threadIdx.x >> 5, lane = threadIdx.x & 31;
    int row = blockIdx.x * 8 + warp;
    if (row >= N_NODES) return;
    float inn = g_innorm[row];
    const float* ar = g_agg + (size_t)row * D;
    srow[warp][lane]      = ar[lane] * inn;
    srow[warp][lane + 32] = ar[lane + 32] * inn;
    __syncwarp();

    float acc0 = sb[lane], acc1 = sb[lane + 32];
#pragma unroll
    for (int k = 0; k < D; k++) {
        float a = srow[warp][k];
        acc0 += a * sW[k * D + lane];
        acc1 += a * sW[k * D + lane + 32];
    }
    if (RELU)     { acc0 = fmaxf(acc0, 0.0f); acc1 = fmaxf(acc1, 0.0f); }
    if (OUTSCALE) { float s = g_outnorm[row]; acc0 *= s; acc1 *= s; }
    out[(size_t)row * D + lane]      = acc0;
    out[(size_t)row * D + lane + 32] = acc1;
}

extern "C" void kernel_launch(void* const* d_in, const int* in_sizes, int n_in,
                              void* d_out, int out_size) {
    const float* emb   = (const float*)d_in[0];
    const float* gc1w  = (const float*)d_in[1];
    const float* gc2w  = (const float*)d_in[2];
    const float* gc1b  = (const float*)d_in[3];
    const float* gc2b  = (const float*)d_in[4];
    const float* p1    = (const float*)d_in[5];
    const float* p2    = (const float*)d_in[6];
    const float* W_ih  = (const float*)d_in[7];
    const float* W_hh  = (const float*)d_in[8];
    const float* b_ih  = (const float*)d_in[9];
    const float* b_hh  = (const float*)d_in[10];
    const int*   src   = (const int*)d_in[11];
    const int*   dst   = (const int*)d_in[12];

    void *p_deg = nullptr, *p_agg = nullptr, *p_w = nullptr, *p_xs = nullptr;
    cudaGetSymbolAddress(&p_deg, g_deg);
    cudaGetSymbolAddress(&p_agg, g_agg);
    cudaGetSymbolAddress(&p_w,   g_w);
    cudaGetSymbolAddress(&p_xs,  g_xs);
    float* w1 = (float*)p_w;
    float* w2 = w1 + H;

    // degrees + norms
    cudaMemsetAsync(p_deg, 0, sizeof(float) * 2 * N_NODES, 0);
    k_degree<<<(N_EDGES + 255) / 256, 256>>>(src, dst);
    k_norms<<<(N_NODES + 255) / 256, 256>>>();

    // layer-1 input prescale (runs while GRU work also queued; same stream, fine)
    k_scale_in<<<(N_NODES * 16 + 255) / 256, 256>>>(emb);

    // GRU weight evolution (both cells fused per weight-row read)
    k_gru_mv<<<2 * (TH / 8), 256>>>(W_ih, W_hh, b_ih, b_hh, p1, p2, gc1w, gc2w);
    k_gru_combine<<<dim3(H / 256, 2), 256>>>(gc1w, gc2w);

    // ---- GCN layer 1 ----
    cudaMemsetAsync(p_agg, 0, sizeof(float) * (size_t)N_NODES * D, 0);
    k_edge<<<(N_EDGES * 16 + 255) / 256, 256>>>(src, dst);
    // writes relu(...)*out_norm into g_xs, ready as layer-2 (pre-scaled) input
    k_transform<true, true><<<N_NODES / 8, 256>>>(w1, gc1b, (float*)p_xs);

    // ---- GCN layer 2 ----
    cudaMemsetAsync(p_agg, 0, sizeof(float) * (size_t)N_NODES * D, 0);
    k_edge<<<(N_EDGES * 16 + 255) / 256, 256>>>(src, dst);
    k_transform<false, false><<<N_NODES / 8, 256>>>(w2, gc2b, (float*)d_out);
}

// round 2
// speedup vs baseline: 1.4775x; 1.4775x over previous
#include <cuda_runtime.h>

#define N_NODES 100000
#define N_EDGES 3200000
#define D 64
#define H 4096
#define TH 12288  // 3*H
#define SCAN_B 1024
#define NSCANBLK ((N_NODES + SCAN_B - 1) / SCAN_B)  // 98

// -------- device scratch (no allocations allowed) --------
__device__ int   g_cnt_out[N_NODES];
__device__ int   g_cnt_in[N_NODES];
__device__ float g_outnorm[N_NODES];
__device__ float g_innorm[N_NODES];
__device__ int   g_rowoff[N_NODES + 1];
__device__ int   g_cursor[N_NODES];
__device__ int   g_bsum[NSCANBLK];
__device__ int   g_boff[NSCANBLK];
__device__ int   g_csr[N_EDGES];              // src ids grouped by dst
__device__ float g_gi[2][TH];
__device__ float g_gh[2][TH];
__device__ float g_w[2][H];
__device__ float g_xs[(size_t)N_NODES * D];   // layer-1 input (out_norm prescaled)
__device__ float g_ys[(size_t)N_NODES * D];   // layer-1 output / layer-2 input

// -------- degree counts (int) --------
__global__ void k_count(const int* __restrict__ src, const int* __restrict__ dst) {
    int e = blockIdx.x * blockDim.x + threadIdx.x;
    if (e >= N_EDGES) return;
    atomicAdd(&g_cnt_out[src[e]], 1);
    atomicAdd(&g_cnt_in[dst[e]], 1);
}

__global__ void k_norms() {
    int i = blockIdx.x * blockDim.x + threadIdx.x;
    if (i >= N_NODES) return;
    g_outnorm[i] = rsqrtf(fmaxf((float)g_cnt_out[i], 1.0f));
    g_innorm[i]  = rsqrtf(fmaxf((float)g_cnt_in[i], 1.0f));
}

// -------- exclusive scan of g_cnt_in -> g_rowoff (3-phase) --------
__global__ void k_scan_local() {
    __shared__ int sh[SCAN_B];
    int tid = threadIdx.x;
    int i = blockIdx.x * SCAN_B + tid;
    int v = (i < N_NODES) ? g_cnt_in[i] : 0;
    sh[tid] = v;
    __syncthreads();
    for (int off = 1; off < SCAN_B; off <<= 1) {
        int t = 0;
        if (tid >= off) t = sh[tid - off];
        __syncthreads();
        if (tid >= off) sh[tid] += t;
        __syncthreads();
    }
    if (i < N_NODES) g_rowoff[i] = sh[tid] - v;  // exclusive, block-local
    if (tid == SCAN_B - 1) g_bsum[blockIdx.x] = sh[tid];
}

__global__ void k_scan_bsum() {
    __shared__ int sh[128];
    int tid = threadIdx.x;
    int v = (tid < NSCANBLK) ? g_bsum[tid] : 0;
    sh[tid] = v;
    __syncthreads();
    for (int off = 1; off < 128; off <<= 1) {
        int t = 0;
        if (tid >= off) t = sh[tid - off];
        __syncthreads();
        if (tid >= off) sh[tid] += t;
        __syncthreads();
    }
    if (tid < NSCANBLK) g_boff[tid] = sh[tid] - v;  // exclusive
}

__global__ void k_scan_add() {
    int i = blockIdx.x * blockDim.x + threadIdx.x;
    if (i >= N_NODES) return;
    int val = g_rowoff[i] + g_boff[i / SCAN_B];
    g_rowoff[i] = val;
    g_cursor[i] = val;
    if (i == 0) g_rowoff[N_NODES] = N_EDGES;
}

// -------- scatter edges into CSR by dst --------
__global__ void k_csr_scatter(const int* __restrict__ src, const int* __restrict__ dst) {
    int e = blockIdx.x * blockDim.x + threadIdx.x;
    if (e >= N_EDGES) return;
    int d = dst[e];
    int pos = atomicAdd(&g_cursor[d], 1);
    g_csr[pos] = src[e];
}

// -------- pre-scale layer-1 input by out_norm --------
__global__ void k_scale_in(const float* __restrict__ x) {
    int t = blockIdx.x * blockDim.x + threadIdx.x;
    if (t >= N_NODES * 16) return;
    int row = t >> 4;
    float4 v = ((const float4*)x)[t];
    float s = g_outnorm[row];
    v.x *= s; v.y *= s; v.z *= s; v.w *= s;
    ((float4*)g_xs)[t] = v;
}

// -------- GRU matvec (unchanged from R1; 76us @ 67.6% DRAM) --------
__global__ void k_gru_mv(const float* __restrict__ W_ih, const float* __restrict__ W_hh,
                         const float* __restrict__ b_ih, const float* __restrict__ b_hh,
                         const float* __restrict__ x1, const float* __restrict__ x2,
                         const float* __restrict__ h1, const float* __restrict__ h2) {
    __shared__ float4 sv1[H / 4];
    __shared__ float4 sv2[H / 4];
    const int HB = TH / 8;
    bool hh = blockIdx.x >= HB;
    const float* W  = hh ? W_hh : W_ih;
    const float* b  = hh ? b_hh : b_ih;
    const float* v1 = hh ? h1 : x1;
    const float* v2 = hh ? h2 : x2;
    float* o1 = hh ? g_gh[0] : g_gi[0];
    float* o2 = hh ? g_gh[1] : g_gi[1];

    for (int i = threadIdx.x; i < H / 4; i += blockDim.x) {
        sv1[i] = ((const float4*)v1)[i];
        sv2[i] = ((const float4*)v2)[i];
    }
    __syncthreads();

    int warp = threadIdx.x >> 5, lane = threadIdx.x & 31;
    int row = (blockIdx.x % HB) * 8 + warp;
    const float4* wr = (const float4*)(W + (size_t)row * H);
    float a1 = 0.0f, a2 = 0.0f;
#pragma unroll 4
    for (int k = lane; k < H / 4; k += 32) {
        float4 w = wr[k];
        float4 p = sv1[k];
        float4 q = sv2[k];
        a1 += w.x * p.x + w.y * p.y + w.z * p.z + w.w * p.w;
        a2 += w.x * q.x + w.y * q.y + w.z * q.z + w.w * q.w;
    }
#pragma unroll
    for (int o = 16; o; o >>= 1) {
        a1 += __shfl_xor_sync(0xffffffffu, a1, o);
        a2 += __shfl_xor_sync(0xffffffffu, a2, o);
    }
    if (lane == 0) {
        float bb = b[row];
        o1[row] = a1 + bb;
        o2[row] = a2 + bb;
    }
}

__device__ __forceinline__ float sigm(float x) { return 1.0f / (1.0f + expf(-x)); }

__global__ void k_gru_combine(const float* __restrict__ gc1w, const float* __restrict__ gc2w) {
    int j = blockIdx.x * blockDim.x + threadIdx.x;
    int c = blockIdx.y;
    if (j >= H) return;
    const float* gi = g_gi[c];
    const float* gh = g_gh[c];
    const float* hv = c ? gc2w : gc1w;
    float r = sigm(gi[j] + gh[j]);
    float z = sigm(gi[H + j] + gh[H + j]);
    float n = tanhf(gi[2 * H + j] + r * gh[2 * H + j]);
    g_w[c][j] = (1.0f - z) * n + z * hv[j];
}

// -------- fused gather-aggregate + in_norm + (row @ W + b) + act [+ out_norm] --------
// one warp per dst node; lane holds float2 of the feature row
template <bool RELU, bool OUTSCALE>
__global__ void k_agg_fused(const float* __restrict__ xin, const float* __restrict__ Wm,
                            const float* __restrict__ bias, float* __restrict__ out) {
    __shared__ float sW[D * D];
    __shared__ float sb[D];
    __shared__ float srow[8][D];
    for (int i = threadIdx.x; i < D * D; i += blockDim.x) sW[i] = Wm[i];
    if (threadIdx.x < D) sb[threadIdx.x] = bias[threadIdx.x];
    __syncthreads();

    int warp = threadIdx.x >> 5, lane = threadIdx.x & 31;
    int node = blockIdx.x * 8 + warp;
    if (node >= N_NODES) return;

    int beg = g_rowoff[node];
    int n = g_rowoff[node + 1] - beg;
    const int* cs = g_csr + beg;
    float accx = 0.0f, accy = 0.0f;
    int e = 0;
    for (; e + 4 <= n; e += 4) {
        int s0 = cs[e], s1 = cs[e + 1], s2 = cs[e + 2], s3 = cs[e + 3];
        float2 v0 = ((const float2*)(xin + (size_t)s0 * D))[lane];
        float2 v1 = ((const float2*)(xin + (size_t)s1 * D))[lane];
        float2 v2 = ((const float2*)(xin + (size_t)s2 * D))[lane];
        float2 v3 = ((const float2*)(xin + (size_t)s3 * D))[lane];
        accx += v0.x + v1.x + v2.x + v3.x;
        accy += v0.y + v1.y + v2.y + v3.y;
    }
    for (; e < n; e++) {
        float2 v = ((const float2*)(xin + (size_t)cs[e] * D))[lane];
        accx += v.x;
        accy += v.y;
    }
    float inn = g_innorm[node];
    srow[warp][2 * lane]     = accx * inn;
    srow[warp][2 * lane + 1] = accy * inn;
    __syncwarp();

    float acc0 = sb[lane], acc1 = sb[lane + 32];
#pragma unroll
    for (int k = 0; k < D; k++) {
        float a = srow[warp][k];
        acc0 += a * sW[k * D + lane];
        acc1 += a * sW[k * D + lane + 32];
    }
    if (RELU)     { acc0 = fmaxf(acc0, 0.0f); acc1 = fmaxf(acc1, 0.0f); }
    if (OUTSCALE) { float s = g_outnorm[node]; acc0 *= s; acc1 *= s; }
    out[(size_t)node * D + lane]      = acc0;
    out[(size_t)node * D + lane + 32] = acc1;
}

extern "C" void kernel_launch(void* const* d_in, const int* in_sizes, int n_in,
                              void* d_out, int out_size) {
    const float* emb   = (const float*)d_in[0];
    const float* gc1w  = (const float*)d_in[1];
    const float* gc2w  = (const float*)d_in[2];
    const float* gc1b  = (const float*)d_in[3];
    const float* gc2b  = (const float*)d_in[4];
    const float* p1    = (const float*)d_in[5];
    const float* p2    = (const float*)d_in[6];
    const float* W_ih  = (const float*)d_in[7];
    const float* W_hh  = (const float*)d_in[8];
    const float* b_ih  = (const float*)d_in[9];
    const float* b_hh  = (const float*)d_in[10];
    const int*   src   = (const int*)d_in[11];
    const int*   dst   = (const int*)d_in[12];

    void *p_co = nullptr, *p_ci = nullptr, *p_w = nullptr, *p_xs = nullptr, *p_ys = nullptr;
    cudaGetSymbolAddress(&p_co, g_cnt_out);
    cudaGetSymbolAddress(&p_ci, g_cnt_in);
    cudaGetSymbolAddress(&p_w,  g_w);
    cudaGetSymbolAddress(&p_xs, g_xs);
    cudaGetSymbolAddress(&p_ys, g_ys);
    float* w1 = (float*)p_w;
    float* w2 = w1 + H;

    // degrees + norms + CSR build
    cudaMemsetAsync(p_co, 0, sizeof(int) * N_NODES, 0);
    cudaMemsetAsync(p_ci, 0, sizeof(int) * N_NODES, 0);
    k_count<<<(N_EDGES + 255) / 256, 256>>>(src, dst);
    k_norms<<<(N_NODES + 255) / 256, 256>>>();
    k_scan_local<<<NSCANBLK, SCAN_B>>>();
    k_scan_bsum<<<1, 128>>>();
    k_scan_add<<<(N_NODES + 255) / 256, 256>>>();
    k_csr_scatter<<<(N_EDGES + 255) / 256, 256>>>(src, dst);

    // layer-1 input prescale
    k_scale_in<<<(N_NODES * 16 + 255) / 256, 256>>>(emb);

    // GRU weight evolution
    k_gru_mv<<<2 * (TH / 8), 256>>>(W_ih, W_hh, b_ih, b_hh, p1, p2, gc1w, gc2w);
    k_gru_combine<<<dim3(H / 256, 2), 256>>>(gc1w, gc2w);

    // ---- GCN layer 1 (gather-agg fused with transform; out_norm folded in) ----
    k_agg_fused<true, true><<<(N_NODES + 7) / 8, 256>>>((const float*)p_xs, w1, gc1b, (float*)p_ys);

    // ---- GCN layer 2 ----
    k_agg_fused<false, false><<<(N_NODES + 7) / 8, 256>>>((const float*)p_ys, w2, gc2b, (float*)d_out);
}

// round 3
// speedup vs baseline: 1.5785x; 1.0683x over previous
#include <cuda_runtime.h>

#define N_NODES 100000
#define N_EDGES 3200000
#define D 64
#define H 4096
#define TH 12288  // 3*H
#define SCAN_B 1024
#define NSCANBLK ((N_NODES + SCAN_B - 1) / SCAN_B)  // 98

// -------- device scratch (no allocations allowed) --------
__device__ int   g_cnt_out[N_NODES];
__device__ int   g_cnt_in[N_NODES];
__device__ float g_outnorm[N_NODES];
__device__ float g_innorm[N_NODES];
__device__ int   g_rowoff[N_NODES + 1];
__device__ int   g_cursor[N_NODES];
__device__ int   g_bsum[NSCANBLK];
__device__ int   g_boff[NSCANBLK];
__device__ int   g_csr[N_EDGES];              // src ids grouped by dst
__device__ float g_gi[2][TH];
__device__ float g_gh[2][TH];
__device__ float g_w[2][H];
__device__ float g_xs[(size_t)N_NODES * D];   // layer-1 input (out_norm prescaled)
__device__ float g_ys[(size_t)N_NODES * D];   // layer-1 output / layer-2 input

// -------- degree counts (int) --------
__global__ void k_count(const int* __restrict__ src, const int* __restrict__ dst) {
    int e = blockIdx.x * blockDim.x + threadIdx.x;
    if (e >= N_EDGES) return;
    atomicAdd(&g_cnt_out[src[e]], 1);
    atomicAdd(&g_cnt_in[dst[e]], 1);
}

__global__ void k_norms() {
    int i = blockIdx.x * blockDim.x + threadIdx.x;
    if (i >= N_NODES) return;
    g_outnorm[i] = rsqrtf(fmaxf((float)g_cnt_out[i], 1.0f));
    g_innorm[i]  = rsqrtf(fmaxf((float)g_cnt_in[i], 1.0f));
}

// -------- exclusive scan of g_cnt_in -> g_rowoff (3-phase) --------
__global__ void k_scan_local() {
    __shared__ int sh[SCAN_B];
    int tid = threadIdx.x;
    int i = blockIdx.x * SCAN_B + tid;
    int v = (i < N_NODES) ? g_cnt_in[i] : 0;
    sh[tid] = v;
    __syncthreads();
    for (int off = 1; off < SCAN_B; off <<= 1) {
        int t = 0;
        if (tid >= off) t = sh[tid - off];
        __syncthreads();
        if (tid >= off) sh[tid] += t;
        __syncthreads();
    }
    if (i < N_NODES) g_rowoff[i] = sh[tid] - v;  // exclusive, block-local
    if (tid == SCAN_B - 1) g_bsum[blockIdx.x] = sh[tid];
}

__global__ void k_scan_bsum() {
    __shared__ int sh[128];
    int tid = threadIdx.x;
    int v = (tid < NSCANBLK) ? g_bsum[tid] : 0;
    sh[tid] = v;
    __syncthreads();
    for (int off = 1; off < 128; off <<= 1) {
        int t = 0;
        if (tid >= off) t = sh[tid - off];
        __syncthreads();
        if (tid >= off) sh[tid] += t;
        __syncthreads();
    }
    if (tid < NSCANBLK) g_boff[tid] = sh[tid] - v;  // exclusive
}

__global__ void k_scan_add() {
    int i = blockIdx.x * blockDim.x + threadIdx.x;
    if (i >= N_NODES) return;
    int val = g_rowoff[i] + g_boff[i / SCAN_B];
    g_rowoff[i] = val;
    g_cursor[i] = val;
    if (i == 0) g_rowoff[N_NODES] = N_EDGES;
}

// -------- scatter edges into CSR by dst --------
__global__ void k_csr_scatter(const int* __restrict__ src, const int* __restrict__ dst) {
    int e = blockIdx.x * blockDim.x + threadIdx.x;
    if (e >= N_EDGES) return;
    int d = dst[e];
    int pos = atomicAdd(&g_cursor[d], 1);
    g_csr[pos] = src[e];
}

// -------- pre-scale layer-1 input by out_norm --------
__global__ void k_scale_in(const float* __restrict__ x) {
    int t = blockIdx.x * blockDim.x + threadIdx.x;
    if (t >= N_NODES * 16) return;
    int row = t >> 4;
    float4 v = ((const float4*)x)[t];
    float s = g_outnorm[row];
    v.x *= s; v.y *= s; v.z *= s; v.w *= s;
    ((float4*)g_xs)[t] = v;
}

// -------- GRU matvec: 512 threads/block (16 rows), both cells per weight-row read --------
__global__ __launch_bounds__(512) void k_gru_mv(
        const float* __restrict__ W_ih, const float* __restrict__ W_hh,
        const float* __restrict__ b_ih, const float* __restrict__ b_hh,
        const float* __restrict__ x1, const float* __restrict__ x2,
        const float* __restrict__ h1, const float* __restrict__ h2) {
    __shared__ float4 sv1[H / 4];
    __shared__ float4 sv2[H / 4];
    const int HB = TH / 16;  // 768 blocks per matrix
    bool hh = blockIdx.x >= HB;
    const float* W  = hh ? W_hh : W_ih;
    const float* b  = hh ? b_hh : b_ih;
    const float* v1 = hh ? h1 : x1;
    const float* v2 = hh ? h2 : x2;
    float* o1 = hh ? g_gh[0] : g_gi[0];
    float* o2 = hh ? g_gh[1] : g_gi[1];

    for (int i = threadIdx.x; i < H / 4; i += blockDim.x) {
        sv1[i] = ((const float4*)v1)[i];
        sv2[i] = ((const float4*)v2)[i];
    }
    __syncthreads();

    int warp = threadIdx.x >> 5, lane = threadIdx.x & 31;
    int row = (blockIdx.x % HB) * 16 + warp;
    const float4* wr = (const float4*)(W + (size_t)row * H);
    float a1 = 0.0f, a2 = 0.0f;
#pragma unroll 8
    for (int k = lane; k < H / 4; k += 32) {
        float4 w = wr[k];
        float4 p = sv1[k];
        float4 q = sv2[k];
        a1 += w.x * p.x + w.y * p.y + w.z * p.z + w.w * p.w;
        a2 += w.x * q.x + w.y * q.y + w.z * q.z + w.w * q.w;
    }
#pragma unroll
    for (int o = 16; o; o >>= 1) {
        a1 += __shfl_xor_sync(0xffffffffu, a1, o);
        a2 += __shfl_xor_sync(0xffffffffu, a2, o);
    }
    if (lane == 0) {
        float bb = b[row];
        o1[row] = a1 + bb;
        o2[row] = a2 + bb;
    }
}

__device__ __forceinline__ float sigm(float x) { return 1.0f / (1.0f + expf(-x)); }

__global__ void k_gru_combine(const float* __restrict__ gc1w, const float* __restrict__ gc2w) {
    int j = blockIdx.x * blockDim.x + threadIdx.x;
    int c = blockIdx.y;
    if (j >= H) return;
    const float* gi = g_gi[c];
    const float* gh = g_gh[c];
    const float* hv = c ? gc2w : gc1w;
    float r = sigm(gi[j] + gh[j]);
    float z = sigm(gi[H + j] + gh[H + j]);
    float n = tanhf(gi[2 * H + j] + r * gh[2 * H + j]);
    g_w[c][j] = (1.0f - z) * n + z * hv[j];
}

// -------- fused gather-aggregate + in_norm + (row @ W + b) + act [+ out_norm] --------
template <bool RELU, bool OUTSCALE>
__global__ void k_agg_fused(const float* __restrict__ xin, const float* __restrict__ Wm,
                            const float* __restrict__ bias, float* __restrict__ out) {
    __shared__ float sW[D * D];
    __shared__ float sb[D];
    __shared__ float srow[8][D];
    for (int i = threadIdx.x; i < D * D; i += blockDim.x) sW[i] = Wm[i];
    if (threadIdx.x < D) sb[threadIdx.x] = bias[threadIdx.x];
    __syncthreads();

    int warp = threadIdx.x >> 5, lane = threadIdx.x & 31;
    int node = blockIdx.x * 8 + warp;
    if (node >= N_NODES) return;

    int beg = g_rowoff[node];
    int n = g_rowoff[node + 1] - beg;
    const int* cs = g_csr + beg;
    float accx = 0.0f, accy = 0.0f;
    int e = 0;
    for (; e + 8 <= n; e += 8) {
        int s0 = __ldg(cs + e),     s1 = __ldg(cs + e + 1);
        int s2 = __ldg(cs + e + 2), s3 = __ldg(cs + e + 3);
        int s4 = __ldg(cs + e + 4), s5 = __ldg(cs + e + 5);
        int s6 = __ldg(cs + e + 6), s7 = __ldg(cs + e + 7);
        float2 v0 = ((const float2*)(xin + (size_t)s0 * D))[lane];
        float2 v1 = ((const float2*)(xin + (size_t)s1 * D))[lane];
        float2 v2 = ((const float2*)(xin + (size_t)s2 * D))[lane];
        float2 v3 = ((const float2*)(xin + (size_t)s3 * D))[lane];
        float2 v4 = ((const float2*)(xin + (size_t)s4 * D))[lane];
        float2 v5 = ((const float2*)(xin + (size_t)s5 * D))[lane];
        float2 v6 = ((const float2*)(xin + (size_t)s6 * D))[lane];
        float2 v7 = ((const float2*)(xin + (size_t)s7 * D))[lane];
        accx += ((v0.x + v1.x) + (v2.x + v3.x)) + ((v4.x + v5.x) + (v6.x + v7.x));
        accy += ((v0.y + v1.y) + (v2.y + v3.y)) + ((v4.y + v5.y) + (v6.y + v7.y));
    }
    for (; e < n; e++) {
        float2 v = ((const float2*)(xin + (size_t)__ldg(cs + e) * D))[lane];
        accx += v.x;
        accy += v.y;
    }
    float inn = g_innorm[node];
    srow[warp][2 * lane]     = accx * inn;
    srow[warp][2 * lane + 1] = accy * inn;
    __syncwarp();

    float acc0 = sb[lane], acc1 = sb[lane + 32];
#pragma unroll
    for (int k = 0; k < D; k++) {
        float a = srow[warp][k];
        acc0 += a * sW[k * D + lane];
        acc1 += a * sW[k * D + lane + 32];
    }
    if (RELU)     { acc0 = fmaxf(acc0, 0.0f); acc1 = fmaxf(acc1, 0.0f); }
    if (OUTSCALE) { float s = g_outnorm[node]; acc0 *= s; acc1 *= s; }
    out[(size_t)node * D + lane]      = acc0;
    out[(size_t)node * D + lane + 32] = acc1;
}

extern "C" void kernel_launch(void* const* d_in, const int* in_sizes, int n_in,
                              void* d_out, int out_size) {
    const float* emb   = (const float*)d_in[0];
    const float* gc1w  = (const float*)d_in[1];
    const float* gc2w  = (const float*)d_in[2];
    const float* gc1b  = (const float*)d_in[3];
    const float* gc2b  = (const float*)d_in[4];
    const float* p1    = (const float*)d_in[5];
    const float* p2    = (const float*)d_in[6];
    const float* W_ih  = (const float*)d_in[7];
    const float* W_hh  = (const float*)d_in[8];
    const float* b_ih  = (const float*)d_in[9];
    const float* b_hh  = (const float*)d_in[10];
    const int*   src   = (const int*)d_in[11];
    const int*   dst   = (const int*)d_in[12];

    void *p_co = nullptr, *p_ci = nullptr, *p_w = nullptr, *p_xs = nullptr, *p_ys = nullptr;
    cudaGetSymbolAddress(&p_co, g_cnt_out);
    cudaGetSymbolAddress(&p_ci, g_cnt_in);
    cudaGetSymbolAddress(&p_w,  g_w);
    cudaGetSymbolAddress(&p_xs, g_xs);
    cudaGetSymbolAddress(&p_ys, g_ys);
    float* w1 = (float*)p_w;
    float* w2 = w1 + H;

    // lazily-created side stream + fork/join events (host resources, no device mem)
    static cudaStream_t s_gru = nullptr;
    static cudaEvent_t  ev_fork = nullptr, ev_join = nullptr;
    if (s_gru == nullptr) {
        cudaStreamCreateWithFlags(&s_gru, cudaStreamNonBlocking);
        cudaEventCreateWithFlags(&ev_fork, cudaEventDisableTiming);
        cudaEventCreateWithFlags(&ev_join, cudaEventDisableTiming);
    }

    // ---- fork: GRU weight evolution on side stream (independent of graph work) ----
    cudaEventRecord(ev_fork, 0);
    cudaStreamWaitEvent(s_gru, ev_fork, 0);
    k_gru_mv<<<2 * (TH / 16), 512, 0, s_gru>>>(W_ih, W_hh, b_ih, b_hh, p1, p2, gc1w, gc2w);
    k_gru_combine<<<dim3(H / 256, 2), 256, 0, s_gru>>>(gc1w, gc2w);
    cudaEventRecord(ev_join, s_gru);

    // ---- main stream: degrees + norms + CSR build + input prescale ----
    cudaMemsetAsync(p_co, 0, sizeof(int) * N_NODES, 0);
    cudaMemsetAsync(p_ci, 0, sizeof(int) * N_NODES, 0);
    k_count<<<(N_EDGES + 255) / 256, 256>>>(src, dst);
    k_norms<<<(N_NODES + 255) / 256, 256>>>();
    k_scan_local<<<NSCANBLK, SCAN_B>>>();
    k_scan_bsum<<<1, 128>>>();
    k_scan_add<<<(N_NODES + 255) / 256, 256>>>();
    k_csr_scatter<<<(N_EDGES + 255) / 256, 256>>>(src, dst);
    k_scale_in<<<(N_NODES * 16 + 255) / 256, 256>>>(emb);

    // ---- join: need evolved w1 before layer 1 ----
    cudaStreamWaitEvent(0, ev_join, 0);

    // ---- GCN layer 1 (gather-agg fused with transform; out_norm folded in) ----
    k_agg_fused<true, true><<<(N_NODES + 7) / 8, 256>>>((const float*)p_xs, w1, gc1b, (float*)p_ys);

    // ---- GCN layer 2 ----
    k_agg_fused<false, false><<<(N_NODES + 7) / 8, 256>>>((const float*)p_ys, w2, gc2b, (float*)d_out);
}

// round 4
// speedup vs baseline: 1.6686x; 1.0571x over previous
#include <cuda_runtime.h>
#include <cuda_fp16.h>

#define N_NODES 100000
#define N_EDGES 3200000
#define D 64
#define H 4096
#define TH 12288  // 3*H
#define SCAN_B 1024
#define NSCANBLK ((N_NODES + SCAN_B - 1) / SCAN_B)  // 98

// -------- device scratch (no allocations allowed) --------
__device__ int    g_cnt_out[N_NODES];
__device__ int    g_cnt_in[N_NODES];
__device__ float  g_outnorm[N_NODES];
__device__ float  g_innorm[N_NODES];
__device__ int    g_rowoff[N_NODES + 1];
__device__ int    g_cursor[N_NODES];
__device__ int    g_bsum[NSCANBLK];
__device__ int    g_boff[NSCANBLK];
__device__ int    g_csr[N_EDGES];               // src ids grouped by dst
__device__ float  g_gi[2][TH];
__device__ float  g_gh[2][TH];
__device__ float  g_w[2][H];
__device__ __half g_xs[(size_t)N_NODES * D];    // layer-1 input (out_norm prescaled, fp16)
__device__ __half g_ys[(size_t)N_NODES * D];    // layer-1 output / layer-2 input (fp16)

// -------- degree counts (int) --------
__global__ void k_count(const int* __restrict__ src, const int* __restrict__ dst) {
    int e = blockIdx.x * blockDim.x + threadIdx.x;
    if (e >= N_EDGES) return;
    atomicAdd(&g_cnt_out[src[e]], 1);
    atomicAdd(&g_cnt_in[dst[e]], 1);
}

__global__ void k_norms() {
    int i = blockIdx.x * blockDim.x + threadIdx.x;
    if (i >= N_NODES) return;
    g_outnorm[i] = rsqrtf(fmaxf((float)g_cnt_out[i], 1.0f));
    g_innorm[i]  = rsqrtf(fmaxf((float)g_cnt_in[i], 1.0f));
}

// -------- exclusive scan of g_cnt_in -> g_rowoff (3-phase) --------
__global__ void k_scan_local() {
    __shared__ int sh[SCAN_B];
    int tid = threadIdx.x;
    int i = blockIdx.x * SCAN_B + tid;
    int v = (i < N_NODES) ? g_cnt_in[i] : 0;
    sh[tid] = v;
    __syncthreads();
    for (int off = 1; off < SCAN_B; off <<= 1) {
        int t = 0;
        if (tid >= off) t = sh[tid - off];
        __syncthreads();
        if (tid >= off) sh[tid] += t;
        __syncthreads();
    }
    if (i < N_NODES) g_rowoff[i] = sh[tid] - v;  // exclusive, block-local
    if (tid == SCAN_B - 1) g_bsum[blockIdx.x] = sh[tid];
}

__global__ void k_scan_bsum() {
    __shared__ int sh[128];
    int tid = threadIdx.x;
    int v = (tid < NSCANBLK) ? g_bsum[tid] : 0;
    sh[tid] = v;
    __syncthreads();
    for (int off = 1; off < 128; off <<= 1) {
        int t = 0;
        if (tid >= off) t = sh[tid - off];
        __syncthreads();
        if (tid >= off) sh[tid] += t;
        __syncthreads();
    }
    if (tid < NSCANBLK) g_boff[tid] = sh[tid] - v;  // exclusive
}

__global__ void k_scan_add() {
    int i = blockIdx.x * blockDim.x + threadIdx.x;
    if (i >= N_NODES) return;
    int val = g_rowoff[i] + g_boff[i / SCAN_B];
    g_rowoff[i] = val;
    g_cursor[i] = val;
    if (i == 0) g_rowoff[N_NODES] = N_EDGES;
}

// -------- scatter edges into CSR by dst --------
__global__ void k_csr_scatter(const int* __restrict__ src, const int* __restrict__ dst) {
    int e = blockIdx.x * blockDim.x + threadIdx.x;
    if (e >= N_EDGES) return;
    int d = dst[e];
    int pos = atomicAdd(&g_cursor[d], 1);
    g_csr[pos] = src[e];
}

// -------- pre-scale layer-1 input by out_norm, convert to fp16 --------
__global__ void k_scale_in(const float* __restrict__ x) {
    int t = blockIdx.x * blockDim.x + threadIdx.x;
    if (t >= N_NODES * 16) return;
    int row = t >> 4;
    float4 v = ((const float4*)x)[t];
    float s = g_outnorm[row];
    __half2 h0 = __floats2half2_rn(v.x * s, v.y * s);
    __half2 h1 = __floats2half2_rn(v.z * s, v.w * s);
    ((__half2*)g_xs)[2 * t]     = h0;
    ((__half2*)g_xs)[2 * t + 1] = h1;
}

// -------- GRU matvec: 512 threads/block (16 rows), both cells per weight-row read --------
__global__ __launch_bounds__(512) void k_gru_mv(
        const float* __restrict__ W_ih, const float* __restrict__ W_hh,
        const float* __restrict__ b_ih, const float* __restrict__ b_hh,
        const float* __restrict__ x1, const float* __restrict__ x2,
        const float* __restrict__ h1, const float* __restrict__ h2) {
    __shared__ float4 sv1[H / 4];
    __shared__ float4 sv2[H / 4];
    const int HB = TH / 16;  // 768 blocks per matrix
    bool hh = blockIdx.x >= HB;
    const float* W  = hh ? W_hh : W_ih;
    const float* b  = hh ? b_hh : b_ih;
    const float* v1 = hh ? h1 : x1;
    const float* v2 = hh ? h2 : x2;
    float* o1 = hh ? g_gh[0] : g_gi[0];
    float* o2 = hh ? g_gh[1] : g_gi[1];

    for (int i = threadIdx.x; i < H / 4; i += blockDim.x) {
        sv1[i] = ((const float4*)v1)[i];
        sv2[i] = ((const float4*)v2)[i];
    }
    __syncthreads();

    int warp = threadIdx.x >> 5, lane = threadIdx.x & 31;
    int row = (blockIdx.x % HB) * 16 + warp;
    const float4* wr = (const float4*)(W + (size_t)row * H);
    float a1 = 0.0f, a2 = 0.0f;
#pragma unroll 8
    for (int k = lane; k < H / 4; k += 32) {
        float4 w = wr[k];
        float4 p = sv1[k];
        float4 q = sv2[k];
        a1 += w.x * p.x + w.y * p.y + w.z * p.z + w.w * p.w;
        a2 += w.x * q.x + w.y * q.y + w.z * q.z + w.w * q.w;
    }
#pragma unroll
    for (int o = 16; o; o >>= 1) {
        a1 += __shfl_xor_sync(0xffffffffu, a1, o);
        a2 += __shfl_xor_sync(0xffffffffu, a2, o);
    }
    if (lane == 0) {
        float bb = b[row];
        o1[row] = a1 + bb;
        o2[row] = a2 + bb;
    }
}

__device__ __forceinline__ float sigm(float x) { return 1.0f / (1.0f + expf(-x)); }

__global__ void k_gru_combine(const float* __restrict__ gc1w, const float* __restrict__ gc2w) {
    int j = blockIdx.x * blockDim.x + threadIdx.x;
    int c = blockIdx.y;
    if (j >= H) return;
    const float* gi = g_gi[c];
    const float* gh = g_gh[c];
    const float* hv = c ? gc2w : gc1w;
    float r = sigm(gi[j] + gh[j]);
    float z = sigm(gi[H + j] + gh[H + j]);
    float n = tanhf(gi[2 * H + j] + r * gh[2 * H + j]);
    g_w[c][j] = (1.0f - z) * n + z * hv[j];
}

// -------- fused gather-aggregate (fp16 gather, fp32 accum) + transform epilogue --------
// HALF_OUT: write fp16 (next layer's gather table); else fp32 (final output)
template <bool RELU, bool OUTSCALE, bool HALF_OUT>
__global__ void k_agg_fused(const __half* __restrict__ xin, const float* __restrict__ Wm,
                            const float* __restrict__ bias, void* __restrict__ outp) {
    __shared__ float sW[D * D];
    __shared__ float sb[D];
    __shared__ float srow[8][D];
    for (int i = threadIdx.x; i < D * D; i += blockDim.x) sW[i] = Wm[i];
    if (threadIdx.x < D) sb[threadIdx.x] = bias[threadIdx.x];
    __syncthreads();

    int warp = threadIdx.x >> 5, lane = threadIdx.x & 31;
    int node = blockIdx.x * 8 + warp;
    if (node >= N_NODES) return;

    int beg = g_rowoff[node];
    int n = g_rowoff[node + 1] - beg;
    const int* cs = g_csr + beg;
    float accx = 0.0f, accy = 0.0f;
    int e = 0;
    for (; e + 8 <= n; e += 8) {
        int s0 = __ldg(cs + e),     s1 = __ldg(cs + e + 1);
        int s2 = __ldg(cs + e + 2), s3 = __ldg(cs + e + 3);
        int s4 = __ldg(cs + e + 4), s5 = __ldg(cs + e + 5);
        int s6 = __ldg(cs + e + 6), s7 = __ldg(cs + e + 7);
        float2 v0 = __half22float2(((const __half2*)(xin + (size_t)s0 * D))[lane]);
        float2 v1 = __half22float2(((const __half2*)(xin + (size_t)s1 * D))[lane]);
        float2 v2 = __half22float2(((const __half2*)(xin + (size_t)s2 * D))[lane]);
        float2 v3 = __half22float2(((const __half2*)(xin + (size_t)s3 * D))[lane]);
        float2 v4 = __half22float2(((const __half2*)(xin + (size_t)s4 * D))[lane]);
        float2 v5 = __half22float2(((const __half2*)(xin + (size_t)s5 * D))[lane]);
        float2 v6 = __half22float2(((const __half2*)(xin + (size_t)s6 * D))[lane]);
        float2 v7 = __half22float2(((const __half2*)(xin + (size_t)s7 * D))[lane]);
        accx += ((v0.x + v1.x) + (v2.x + v3.x)) + ((v4.x + v5.x) + (v6.x + v7.x));
        accy += ((v0.y + v1.y) + (v2.y + v3.y)) + ((v4.y + v5.y) + (v6.y + v7.y));
    }
    for (; e < n; e++) {
        float2 v = __half22float2(((const __half2*)(xin + (size_t)__ldg(cs + e) * D))[lane]);
        accx += v.x;
        accy += v.y;
    }
    float inn = g_innorm[node];
    srow[warp][2 * lane]     = accx * inn;
    srow[warp][2 * lane + 1] = accy * inn;
    __syncwarp();

    float acc0 = sb[lane], acc1 = sb[lane + 32];
#pragma unroll
    for (int k = 0; k < D; k++) {
        float a = srow[warp][k];
        acc0 += a * sW[k * D + lane];
        acc1 += a * sW[k * D + lane + 32];
    }
    if (RELU)     { acc0 = fmaxf(acc0, 0.0f); acc1 = fmaxf(acc1, 0.0f); }
    if (OUTSCALE) { float s = g_outnorm[node]; acc0 *= s; acc1 *= s; }
    if (HALF_OUT) {
        __half* out = (__half*)outp;
        out[(size_t)node * D + lane]      = __float2half_rn(acc0);
        out[(size_t)node * D + lane + 32] = __float2half_rn(acc1);
    } else {
        float* out = (float*)outp;
        out[(size_t)node * D + lane]      = acc0;
        out[(size_t)node * D + lane + 32] = acc1;
    }
}

extern "C" void kernel_launch(void* const* d_in, const int* in_sizes, int n_in,
                              void* d_out, int out_size) {
    const float* emb   = (const float*)d_in[0];
    const float* gc1w  = (const float*)d_in[1];
    const float* gc2w  = (const float*)d_in[2];
    const float* gc1b  = (const float*)d_in[3];
    const float* gc2b  = (const float*)d_in[4];
    const float* p1    = (const float*)d_in[5];
    const float* p2    = (const float*)d_in[6];
    const float* W_ih  = (const float*)d_in[7];
    const float* W_hh  = (const float*)d_in[8];
    const float* b_ih  = (const float*)d_in[9];
    const float* b_hh  = (const float*)d_in[10];
    const int*   src   = (const int*)d_in[11];
    const int*   dst   = (const int*)d_in[12];

    void *p_co = nullptr, *p_ci = nullptr, *p_w = nullptr, *p_xs = nullptr, *p_ys = nullptr;
    cudaGetSymbolAddress(&p_co, g_cnt_out);
    cudaGetSymbolAddress(&p_ci, g_cnt_in);
    cudaGetSymbolAddress(&p_w,  g_w);
    cudaGetSymbolAddress(&p_xs, g_xs);
    cudaGetSymbolAddress(&p_ys, g_ys);
    float* w1 = (float*)p_w;
    float* w2 = w1 + H;

    // lazily-created side streams + fork/join events (host resources, no device mem)
    static cudaStream_t s_gru = nullptr, s_pre = nullptr;
    static cudaEvent_t  ev_fork = nullptr, ev_join = nullptr;
    static cudaEvent_t  ev_norms = nullptr, ev_scale = nullptr;
    if (s_gru == nullptr) {
        cudaStreamCreateWithFlags(&s_gru, cudaStreamNonBlocking);
        cudaStreamCreateWithFlags(&s_pre, cudaStreamNonBlocking);
        cudaEventCreateWithFlags(&ev_fork,  cudaEventDisableTiming);
        cudaEventCreateWithFlags(&ev_join,  cudaEventDisableTiming);
        cudaEventCreateWithFlags(&ev_norms, cudaEventDisableTiming);
        cudaEventCreateWithFlags(&ev_scale, cudaEventDisableTiming);
    }

    // ---- fork: GRU weight evolution on side stream (independent of graph work) ----
    cudaEventRecord(ev_fork, 0);
    cudaStreamWaitEvent(s_gru, ev_fork, 0);
    k_gru_mv<<<2 * (TH / 16), 512, 0, s_gru>>>(W_ih, W_hh, b_ih, b_hh, p1, p2, gc1w, gc2w);
    k_gru_combine<<<dim3(H / 256, 2), 256, 0, s_gru>>>(gc1w, gc2w);
    cudaEventRecord(ev_join, s_gru);

    // ---- main stream: degrees + norms ----
    cudaMemsetAsync(p_co, 0, sizeof(int) * N_NODES, 0);
    cudaMemsetAsync(p_ci, 0, sizeof(int) * N_NODES, 0);
    k_count<<<(N_EDGES + 255) / 256, 256>>>(src, dst);
    k_norms<<<(N_NODES + 255) / 256, 256>>>();

    // ---- fork: input prescale (needs only out_norm) overlaps scan+scatter ----
    cudaEventRecord(ev_norms, 0);
    cudaStreamWaitEvent(s_pre, ev_norms, 0);
    k_scale_in<<<(N_NODES * 16 + 255) / 256, 256, 0, s_pre>>>(emb);
    cudaEventRecord(ev_scale, s_pre);

    // ---- main stream: scan + CSR scatter ----
    k_scan_local<<<NSCANBLK, SCAN_B>>>();
    k_scan_bsum<<<1, 128>>>();
    k_scan_add<<<(N_NODES + 255) / 256, 256>>>();
    k_csr_scatter<<<(N_EDGES + 255) / 256, 256>>>(src, dst);

    // ---- join: need evolved w1 + prescaled input before layer 1 ----
    cudaStreamWaitEvent(0, ev_join, 0);
    cudaStreamWaitEvent(0, ev_scale, 0);

    // ---- GCN layer 1 (gather-agg fused with transform; out_norm folded in, fp16 out) ----
    k_agg_fused<true, true, true><<<(N_NODES + 7) / 8, 256>>>(
        (const __half*)p_xs, w1, gc1b, p_ys);

    // ---- GCN layer 2 (fp32 final output) ----
    k_agg_fused<false, false, false><<<(N_NODES + 7) / 8, 256>>>(
        (const __half*)p_ys, w2, gc2b, d_out);
}

// round 5
// speedup vs baseline: 1.7186x; 1.0300x over previous
#include <cuda_runtime.h>
#include <cuda_fp16.h>

#define N_NODES 100000
#define N_EDGES 3200000
#define D 64
#define H 4096
#define TH 12288  // 3*H
#define SCAN_B 1024
#define NSCANBLK ((N_NODES + SCAN_B - 1) / SCAN_B)  // 98
#define AGG_BLOCKS 592
#define AGG_THREADS 512

// -------- device scratch (no allocations allowed) --------
__device__ int    g_cnt_out[N_NODES];
__device__ int    g_cnt_in[N_NODES];
__device__ float  g_outnorm[N_NODES];
__device__ float  g_innorm[N_NODES];
__device__ int    g_rowoff[N_NODES + 1];
__device__ int    g_cursor[N_NODES];
__device__ int    g_bsum[NSCANBLK];
__device__ int    g_boff[NSCANBLK];
__device__ int    g_csr[N_EDGES];               // src ids grouped by dst
__device__ float  g_gi[2][TH];
__device__ float  g_gh[2][TH];
__device__ float  g_w[2][H];
__device__ __half g_xs[(size_t)N_NODES * D];    // layer-1 input (out_norm prescaled, fp16)
__device__ __half g_ys[(size_t)N_NODES * D];    // layer-1 output / layer-2 input (fp16)

// -------- degree counts (int), 4 edges per thread --------
__global__ void k_count(const int4* __restrict__ src4, const int4* __restrict__ dst4) {
    int t = blockIdx.x * blockDim.x + threadIdx.x;
    if (t >= N_EDGES / 4) return;
    int4 s = src4[t];
    int4 d = dst4[t];
    atomicAdd(&g_cnt_out[s.x], 1); atomicAdd(&g_cnt_out[s.y], 1);
    atomicAdd(&g_cnt_out[s.z], 1); atomicAdd(&g_cnt_out[s.w], 1);
    atomicAdd(&g_cnt_in[d.x], 1);  atomicAdd(&g_cnt_in[d.y], 1);
    atomicAdd(&g_cnt_in[d.z], 1);  atomicAdd(&g_cnt_in[d.w], 1);
}

__global__ void k_norms() {
    int i = blockIdx.x * blockDim.x + threadIdx.x;
    if (i >= N_NODES) return;
    g_outnorm[i] = rsqrtf(fmaxf((float)g_cnt_out[i], 1.0f));
    g_innorm[i]  = rsqrtf(fmaxf((float)g_cnt_in[i], 1.0f));
}

// -------- exclusive scan of g_cnt_in -> g_rowoff (3-phase) --------
__global__ void k_scan_local() {
    __shared__ int sh[SCAN_B];
    int tid = threadIdx.x;
    int i = blockIdx.x * SCAN_B + tid;
    int v = (i < N_NODES) ? g_cnt_in[i] : 0;
    sh[tid] = v;
    __syncthreads();
    for (int off = 1; off < SCAN_B; off <<= 1) {
        int t = 0;
        if (tid >= off) t = sh[tid - off];
        __syncthreads();
        if (tid >= off) sh[tid] += t;
        __syncthreads();
    }
    if (i < N_NODES) g_rowoff[i] = sh[tid] - v;  // exclusive, block-local
    if (tid == SCAN_B - 1) g_bsum[blockIdx.x] = sh[tid];
}

__global__ void k_scan_bsum() {
    __shared__ int sh[128];
    int tid = threadIdx.x;
    int v = (tid < NSCANBLK) ? g_bsum[tid] : 0;
    sh[tid] = v;
    __syncthreads();
    for (int off = 1; off < 128; off <<= 1) {
        int t = 0;
        if (tid >= off) t = sh[tid - off];
        __syncthreads();
        if (tid >= off) sh[tid] += t;
        __syncthreads();
    }
    if (tid < NSCANBLK) g_boff[tid] = sh[tid] - v;  // exclusive
}

__global__ void k_scan_add() {
    int i = blockIdx.x * blockDim.x + threadIdx.x;
    if (i >= N_NODES) return;
    int val = g_rowoff[i] + g_boff[i / SCAN_B];
    g_rowoff[i] = val;
    g_cursor[i] = val;
    if (i == 0) g_rowoff[N_NODES] = N_EDGES;
}

// -------- scatter edges into CSR by dst, 4 edges per thread --------
__global__ void k_csr_scatter(const int4* __restrict__ src4, const int4* __restrict__ dst4) {
    int t = blockIdx.x * blockDim.x + threadIdx.x;
    if (t >= N_EDGES / 4) return;
    int4 s = src4[t];
    int4 d = dst4[t];
    g_csr[atomicAdd(&g_cursor[d.x], 1)] = s.x;
    g_csr[atomicAdd(&g_cursor[d.y], 1)] = s.y;
    g_csr[atomicAdd(&g_cursor[d.z], 1)] = s.z;
    g_csr[atomicAdd(&g_cursor[d.w], 1)] = s.w;
}

// -------- pre-scale layer-1 input by out_norm, convert to fp16 --------
__global__ void k_scale_in(const float* __restrict__ x) {
    int t = blockIdx.x * blockDim.x + threadIdx.x;
    if (t >= N_NODES * 16) return;
    int row = t >> 4;
    float4 v = ((const float4*)x)[t];
    float s = g_outnorm[row];
    __half2 h0 = __floats2half2_rn(v.x * s, v.y * s);
    __half2 h1 = __floats2half2_rn(v.z * s, v.w * s);
    ((__half2*)g_xs)[2 * t]     = h0;
    ((__half2*)g_xs)[2 * t + 1] = h1;
}

// -------- GRU matvec: 512 threads/block (16 rows), both cells per weight-row read --------
__global__ __launch_bounds__(512) void k_gru_mv(
        const float* __restrict__ W_ih, const float* __restrict__ W_hh,
        const float* __restrict__ b_ih, const float* __restrict__ b_hh,
        const float* __restrict__ x1, const float* __restrict__ x2,
        const float* __restrict__ h1, const float* __restrict__ h2) {
    __shared__ float4 sv1[H / 4];
    __shared__ float4 sv2[H / 4];
    const int HB = TH / 16;  // 768 blocks per matrix
    bool hh = blockIdx.x >= HB;
    const float* W  = hh ? W_hh : W_ih;
    const float* b  = hh ? b_hh : b_ih;
    const float* v1 = hh ? h1 : x1;
    const float* v2 = hh ? h2 : x2;
    float* o1 = hh ? g_gh[0] : g_gi[0];
    float* o2 = hh ? g_gh[1] : g_gi[1];

    for (int i = threadIdx.x; i < H / 4; i += blockDim.x) {
        sv1[i] = ((const float4*)v1)[i];
        sv2[i] = ((const float4*)v2)[i];
    }
    __syncthreads();

    int warp = threadIdx.x >> 5, lane = threadIdx.x & 31;
    int row = (blockIdx.x % HB) * 16 + warp;
    const float4* wr = (const float4*)(W + (size_t)row * H);
    float a1 = 0.0f, a2 = 0.0f;
#pragma unroll 8
    for (int k = lane; k < H / 4; k += 32) {
        float4 w = wr[k];
        float4 p = sv1[k];
        float4 q = sv2[k];
        a1 += w.x * p.x + w.y * p.y + w.z * p.z + w.w * p.w;
        a2 += w.x * q.x + w.y * q.y + w.z * q.z + w.w * q.w;
    }
#pragma unroll
    for (int o = 16; o; o >>= 1) {
        a1 += __shfl_xor_sync(0xffffffffu, a1, o);
        a2 += __shfl_xor_sync(0xffffffffu, a2, o);
    }
    if (lane == 0) {
        float bb = b[row];
        o1[row] = a1 + bb;
        o2[row] = a2 + bb;
    }
}

__device__ __forceinline__ float sigm(float x) { return 1.0f / (1.0f + expf(-x)); }

__global__ void k_gru_combine(const float* __restrict__ gc1w, const float* __restrict__ gc2w) {
    int j = blockIdx.x * blockDim.x + threadIdx.x;
    int c = blockIdx.y;
    if (j >= H) return;
    const float* gi = g_gi[c];
    const float* gh = g_gh[c];
    const float* hv = c ? gc2w : gc1w;
    float r = sigm(gi[j] + gh[j]);
    float z = sigm(gi[H + j] + gh[H + j]);
    float n = tanhf(gi[2 * H + j] + r * gh[2 * H + j]);
    g_w[c][j] = (1.0f - z) * n + z * hv[j];
}

// -------- persistent fused gather-aggregate + transform epilogue --------
// 592 blocks x 512 threads; each warp grid-strides over nodes.
// Weight smem load happens once per block (592x) instead of once per 8 nodes (12500x).
template <bool RELU, bool OUTSCALE, bool HALF_OUT>
__global__ __launch_bounds__(AGG_THREADS) void k_agg_fused(
        const __half* __restrict__ xin, const float* __restrict__ Wm,
        const float* __restrict__ bias, void* __restrict__ outp) {
    __shared__ float sW[D * D];
    __shared__ float sb[D];
    __shared__ float srow[AGG_THREADS / 32][D];
    for (int i = threadIdx.x; i < D * D; i += blockDim.x) sW[i] = Wm[i];
    if (threadIdx.x < D) sb[threadIdx.x] = bias[threadIdx.x];
    __syncthreads();

    int warp = threadIdx.x >> 5, lane = threadIdx.x & 31;
    int gwarp = (blockIdx.x * AGG_THREADS + threadIdx.x) >> 5;
    const int nwarps = AGG_BLOCKS * (AGG_THREADS / 32);

    for (int node = gwarp; node < N_NODES; node += nwarps) {
        int beg = g_rowoff[node];
        int n = g_rowoff[node + 1] - beg;
        const int* cs = g_csr + beg;
        float accx = 0.0f, accy = 0.0f;
        int e = 0;
        for (; e + 8 <= n; e += 8) {
            int s0 = __ldg(cs + e),     s1 = __ldg(cs + e + 1);
            int s2 = __ldg(cs + e + 2), s3 = __ldg(cs + e + 3);
            int s4 = __ldg(cs + e + 4), s5 = __ldg(cs + e + 5);
            int s6 = __ldg(cs + e + 6), s7 = __ldg(cs + e + 7);
            float2 v0 = __half22float2(((const __half2*)(xin + (size_t)s0 * D))[lane]);
            float2 v1 = __half22float2(((const __half2*)(xin + (size_t)s1 * D))[lane]);
            float2 v2 = __half22float2(((const __half2*)(xin + (size_t)s2 * D))[lane]);
            float2 v3 = __half22float2(((const __half2*)(xin + (size_t)s3 * D))[lane]);
            float2 v4 = __half22float2(((const __half2*)(xin + (size_t)s4 * D))[lane]);
            float2 v5 = __half22float2(((const __half2*)(xin + (size_t)s5 * D))[lane]);
            float2 v6 = __half22float2(((const __half2*)(xin + (size_t)s6 * D))[lane]);
            float2 v7 = __half22float2(((const __half2*)(xin + (size_t)s7 * D))[lane]);
            accx += ((v0.x + v1.x) + (v2.x + v3.x)) + ((v4.x + v5.x) + (v6.x + v7.x));
            accy += ((v0.y + v1.y) + (v2.y + v3.y)) + ((v4.y + v5.y) + (v6.y + v7.y));
        }
        for (; e < n; e++) {
            float2 v = __half22float2(((const __half2*)(xin + (size_t)__ldg(cs + e) * D))[lane]);
            accx += v.x;
            accy += v.y;
        }
        float inn = g_innorm[node];
        srow[warp][2 * lane]     = accx * inn;
        srow[warp][2 * lane + 1] = accy * inn;
        __syncwarp();

        float acc0 = sb[lane], acc1 = sb[lane + 32];
#pragma unroll
        for (int k = 0; k < D; k++) {
            float a = srow[warp][k];
            acc0 += a * sW[k * D + lane];
            acc1 += a * sW[k * D + lane + 32];
        }
        if (RELU)     { acc0 = fmaxf(acc0, 0.0f); acc1 = fmaxf(acc1, 0.0f); }
        if (OUTSCALE) { float s = g_outnorm[node]; acc0 *= s; acc1 *= s; }
        if (HALF_OUT) {
            __half* out = (__half*)outp;
            out[(size_t)node * D + lane]      = __float2half_rn(acc0);
            out[(size_t)node * D + lane + 32] = __float2half_rn(acc1);
        } else {
            float* out = (float*)outp;
            out[(size_t)node * D + lane]      = acc0;
            out[(size_t)node * D + lane + 32] = acc1;
        }
        __syncwarp();
    }
}

extern "C" void kernel_launch(void* const* d_in, const int* in_sizes, int n_in,
                              void* d_out, int out_size) {
    const float* emb   = (const float*)d_in[0];
    const float* gc1w  = (const float*)d_in[1];
    const float* gc2w  = (const float*)d_in[2];
    const float* gc1b  = (const float*)d_in[3];
    const float* gc2b  = (const float*)d_in[4];
    const float* p1    = (const float*)d_in[5];
    const float* p2    = (const float*)d_in[6];
    const float* W_ih  = (const float*)d_in[7];
    const float* W_hh  = (const float*)d_in[8];
    const float* b_ih  = (const float*)d_in[9];
    const float* b_hh  = (const float*)d_in[10];
    const int*   src   = (const int*)d_in[11];
    const int*   dst   = (const int*)d_in[12];

    void *p_co = nullptr, *p_ci = nullptr, *p_w = nullptr, *p_xs = nullptr, *p_ys = nullptr;
    cudaGetSymbolAddress(&p_co, g_cnt_out);
    cudaGetSymbolAddress(&p_ci, g_cnt_in);
    cudaGetSymbolAddress(&p_w,  g_w);
    cudaGetSymbolAddress(&p_xs, g_xs);
    cudaGetSymbolAddress(&p_ys, g_ys);
    float* w1 = (float*)p_w;
    float* w2 = w1 + H;

    // lazily-created side streams + fork/join events (host resources, no device mem)
    static cudaStream_t s_gru = nullptr, s_pre = nullptr;
    static cudaEvent_t  ev_fork = nullptr, ev_join = nullptr;
    static cudaEvent_t  ev_norms = nullptr, ev_scale = nullptr;
    if (s_gru == nullptr) {
        cudaStreamCreateWithFlags(&s_gru, cudaStreamNonBlocking);
        cudaStreamCreateWithFlags(&s_pre, cudaStreamNonBlocking);
        cudaEventCreateWithFlags(&ev_fork,  cudaEventDisableTiming);
        cudaEventCreateWithFlags(&ev_join,  cudaEventDisableTiming);
        cudaEventCreateWithFlags(&ev_norms, cudaEventDisableTiming);
        cudaEventCreateWithFlags(&ev_scale, cudaEventDisableTiming);
    }

    // ---- fork: GRU weight evolution on side stream (independent of graph work) ----
    cudaEventRecord(ev_fork, 0);
    cudaStreamWaitEvent(s_gru, ev_fork, 0);
    k_gru_mv<<<2 * (TH / 16), 512, 0, s_gru>>>(W_ih, W_hh, b_ih, b_hh, p1, p2, gc1w, gc2w);
    k_gru_combine<<<dim3(H / 256, 2), 256, 0, s_gru>>>(gc1w, gc2w);
    cudaEventRecord(ev_join, s_gru);

    // ---- main stream: degrees + norms ----
    cudaMemsetAsync(p_co, 0, sizeof(int) * N_NODES, 0);
    cudaMemsetAsync(p_ci, 0, sizeof(int) * N_NODES, 0);
    k_count<<<(N_EDGES / 4 + 255) / 256, 256>>>((const int4*)src, (const int4*)dst);
    k_norms<<<(N_NODES + 255) / 256, 256>>>();

    // ---- fork: input prescale (needs only out_norm) overlaps scan+scatter ----
    cudaEventRecord(ev_norms, 0);
    cudaStreamWaitEvent(s_pre, ev_norms, 0);
    k_scale_in<<<(N_NODES * 16 + 255) / 256, 256, 0, s_pre>>>(emb);
    cudaEventRecord(ev_scale, s_pre);

    // ---- main stream: scan + CSR scatter ----
    k_scan_local<<<NSCANBLK, SCAN_B>>>();
    k_scan_bsum<<<1, 128>>>();
    k_scan_add<<<(N_NODES + 255) / 256, 256>>>();
    k_csr_scatter<<<(N_EDGES / 4 + 255) / 256, 256>>>((const int4*)src, (const int4*)dst);

    // ---- join: need evolved w1 + prescaled input before layer 1 ----
    cudaStreamWaitEvent(0, ev_join, 0);
    cudaStreamWaitEvent(0, ev_scale, 0);

    // ---- GCN layer 1 (persistent gather-agg fused with transform; fp16 out) ----
    k_agg_fused<true, true, true><<<AGG_BLOCKS, AGG_THREADS>>>(
        (const __half*)p_xs, w1, gc1b, p_ys);

    // ---- GCN layer 2 (fp32 final output) ----
    k_agg_fused<false, false, false><<<AGG_BLOCKS, AGG_THREADS>>>(
        (const __half*)p_ys, w2, gc2b, d_out);
}

// round 6
// speedup vs baseline: 1.8035x; 1.0494x over previous
#include <cuda_runtime.h>
#include <cuda_fp16.h>
#include <mma.h>

#define N_NODES 100000
#define N_EDGES 3200000
#define D 64
#define H 4096
#define TH 12288  // 3*H
#define SCAN_B 1024
#define NSCANBLK ((N_NODES + SCAN_B - 1) / SCAN_B)  // 98
#define AGG_BLOCKS 592
#define AGG_THREADS 512

using namespace nvcuda;

// -------- device scratch (no allocations allowed) --------
__device__ int    g_cnt_out[N_NODES];
__device__ int    g_cnt_in[N_NODES];
__device__ float  g_outnorm[N_NODES];
__device__ float  g_innorm[N_NODES];
__device__ int    g_rowoff[N_NODES + 1];
__device__ int    g_cursor[N_NODES];
__device__ int    g_bsum[NSCANBLK];
__device__ int    g_boff[NSCANBLK];
__device__ int    g_csr[N_EDGES];               // src ids grouped by dst
__device__ float  g_gi[2][TH];
__device__ float  g_gh[2][TH];
__device__ __half g_wh[2][H];                   // evolved weights, fp16 (for wmma)
__device__ __half g_xs[(size_t)N_NODES * D];    // layer-1 input (out_norm prescaled, fp16)
__device__ __half g_ys[(size_t)N_NODES * D];    // layer-1 output / layer-2 input (fp16)
__device__ __half g_agg_h[(size_t)N_NODES * D]; // aggregated rows (in_norm applied, fp16)

// -------- degree counts (int), 4 edges per thread --------
__global__ void k_count(const int4* __restrict__ src4, const int4* __restrict__ dst4) {
    int t = blockIdx.x * blockDim.x + threadIdx.x;
    if (t >= N_EDGES / 4) return;
    int4 s = src4[t];
    int4 d = dst4[t];
    atomicAdd(&g_cnt_out[s.x], 1); atomicAdd(&g_cnt_out[s.y], 1);
    atomicAdd(&g_cnt_out[s.z], 1); atomicAdd(&g_cnt_out[s.w], 1);
    atomicAdd(&g_cnt_in[d.x], 1);  atomicAdd(&g_cnt_in[d.y], 1);
    atomicAdd(&g_cnt_in[d.z], 1);  atomicAdd(&g_cnt_in[d.w], 1);
}

__global__ void k_norms() {
    int i = blockIdx.x * blockDim.x + threadIdx.x;
    if (i >= N_NODES) return;
    g_outnorm[i] = rsqrtf(fmaxf((float)g_cnt_out[i], 1.0f));
    g_innorm[i]  = rsqrtf(fmaxf((float)g_cnt_in[i], 1.0f));
}

// -------- exclusive scan of g_cnt_in -> g_rowoff (3-phase) --------
__global__ void k_scan_local() {
    __shared__ int sh[SCAN_B];
    int tid = threadIdx.x;
    int i = blockIdx.x * SCAN_B + tid;
    int v = (i < N_NODES) ? g_cnt_in[i] : 0;
    sh[tid] = v;
    __syncthreads();
    for (int off = 1; off < SCAN_B; off <<= 1) {
        int t = 0;
        if (tid >= off) t = sh[tid - off];
        __syncthreads();
        if (tid >= off) sh[tid] += t;
        __syncthreads();
    }
    if (i < N_NODES) g_rowoff[i] = sh[tid] - v;  // exclusive, block-local
    if (tid == SCAN_B - 1) g_bsum[blockIdx.x] = sh[tid];
}

__global__ void k_scan_bsum() {
    __shared__ int sh[128];
    int tid = threadIdx.x;
    int v = (tid < NSCANBLK) ? g_bsum[tid] : 0;
    sh[tid] = v;
    __syncthreads();
    for (int off = 1; off < 128; off <<= 1) {
        int t = 0;
        if (tid >= off) t = sh[tid - off];
        __syncthreads();
        if (tid >= off) sh[tid] += t;
        __syncthreads();
    }
    if (tid < NSCANBLK) g_boff[tid] = sh[tid] - v;  // exclusive
}

__global__ void k_scan_add() {
    int i = blockIdx.x * blockDim.x + threadIdx.x;
    if (i >= N_NODES) return;
    int val = g_rowoff[i] + g_boff[i / SCAN_B];
    g_rowoff[i] = val;
    g_cursor[i] = val;
    if (i == 0) g_rowoff[N_NODES] = N_EDGES;
}

// -------- scatter edges into CSR by dst, 4 edges per thread --------
__global__ void k_csr_scatter(const int4* __restrict__ src4, const int4* __restrict__ dst4) {
    int t = blockIdx.x * blockDim.x + threadIdx.x;
    if (t >= N_EDGES / 4) return;
    int4 s = src4[t];
    int4 d = dst4[t];
    g_csr[atomicAdd(&g_cursor[d.x], 1)] = s.x;
    g_csr[atomicAdd(&g_cursor[d.y], 1)] = s.y;
    g_csr[atomicAdd(&g_cursor[d.z], 1)] = s.z;
    g_csr[atomicAdd(&g_cursor[d.w], 1)] = s.w;
}

// -------- pre-scale layer-1 input by out_norm, convert to fp16 --------
__global__ void k_scale_in(const float* __restrict__ x) {
    int t = blockIdx.x * blockDim.x + threadIdx.x;
    if (t >= N_NODES * 16) return;
    int row = t >> 4;
    float4 v = ((const float4*)x)[t];
    float s = g_outnorm[row];
    __half2 h0 = __floats2half2_rn(v.x * s, v.y * s);
    __half2 h1 = __floats2half2_rn(v.z * s, v.w * s);
    ((__half2*)g_xs)[2 * t]     = h0;
    ((__half2*)g_xs)[2 * t + 1] = h1;
}

// -------- GRU matvec: 512 threads/block (16 rows), both cells per weight-row read --------
__global__ __launch_bounds__(512) void k_gru_mv(
        const float* __restrict__ W_ih, const float* __restrict__ W_hh,
        const float* __restrict__ b_ih, const float* __restrict__ b_hh,
        const float* __restrict__ x1, const float* __restrict__ x2,
        const float* __restrict__ h1, const float* __restrict__ h2) {
    __shared__ float4 sv1[H / 4];
    __shared__ float4 sv2[H / 4];
    const int HB = TH / 16;  // 768 blocks per matrix
    bool hh = blockIdx.x >= HB;
    const float* W  = hh ? W_hh : W_ih;
    const float* b  = hh ? b_hh : b_ih;
    const float* v1 = hh ? h1 : x1;
    const float* v2 = hh ? h2 : x2;
    float* o1 = hh ? g_gh[0] : g_gi[0];
    float* o2 = hh ? g_gh[1] : g_gi[1];

    for (int i = threadIdx.x; i < H / 4; i += blockDim.x) {
        sv1[i] = ((const float4*)v1)[i];
        sv2[i] = ((const float4*)v2)[i];
    }
    __syncthreads();

    int warp = threadIdx.x >> 5, lane = threadIdx.x & 31;
    int row = (blockIdx.x % HB) * 16 + warp;
    const float4* wr = (const float4*)(W + (size_t)row * H);
    float a1 = 0.0f, a2 = 0.0f;
#pragma unroll 8
    for (int k = lane; k < H / 4; k += 32) {
        float4 w = wr[k];
        float4 p = sv1[k];
        float4 q = sv2[k];
        a1 += w.x * p.x + w.y * p.y + w.z * p.z + w.w * p.w;
        a2 += w.x * q.x + w.y * q.y + w.z * q.z + w.w * q.w;
    }
#pragma unroll
    for (int o = 16; o; o >>= 1) {
        a1 += __shfl_xor_sync(0xffffffffu, a1, o);
        a2 += __shfl_xor_sync(0xffffffffu, a2, o);
    }
    if (lane == 0) {
        float bb = b[row];
        o1[row] = a1 + bb;
        o2[row] = a2 + bb;
    }
}

__device__ __forceinline__ float sigm(float x) { return 1.0f / (1.0f + expf(-x)); }

// combine gates -> evolved weight, stored directly as fp16 for the wmma transform
__global__ void k_gru_combine(const float* __restrict__ gc1w, const float* __restrict__ gc2w) {
    int j = blockIdx.x * blockDim.x + threadIdx.x;
    int c = blockIdx.y;
    if (j >= H) return;
    const float* gi = g_gi[c];
    const float* gh = g_gh[c];
    const float* hv = c ? gc2w : gc1w;
    float r = sigm(gi[j] + gh[j]);
    float z = sigm(gi[H + j] + gh[H + j]);
    float n = tanhf(gi[2 * H + j] + r * gh[2 * H + j]);
    g_wh[c][j] = __float2half_rn((1.0f - z) * n + z * hv[j]);
}

// -------- persistent gather-aggregate: 16 lanes per node, 2 nodes per warp --------
// lane sub (0..15) holds features [4*sub .. 4*sub+3] as uint2 (4 halves = 8B);
// one warp-wide load instruction serves 2 edges (one per half-warp).
__global__ __launch_bounds__(AGG_THREADS) void k_agg(const __half* __restrict__ xin) {
    int lane = threadIdx.x & 31;
    int sub = lane & 15;
    int grp = lane >> 4;  // 0 or 1
    int gwarp = (blockIdx.x * AGG_THREADS + threadIdx.x) >> 5;
    const int nwarps = AGG_BLOCKS * (AGG_THREADS / 32);

    for (int base = gwarp * 2; base < N_NODES; base += nwarps * 2) {
        int node = base + grp;  // N_NODES even -> always < N_NODES
        int beg = g_rowoff[node];
        int n = g_rowoff[node + 1] - beg;
        const int* cs = g_csr + beg;
        float ax = 0.0f, ay = 0.0f, az = 0.0f, aw = 0.0f;
        int e = 0;
        for (; e + 4 <= n; e += 4) {
            int s0 = __ldg(cs + e),     s1 = __ldg(cs + e + 1);
            int s2 = __ldg(cs + e + 2), s3 = __ldg(cs + e + 3);
            uint2 u0 = ((const uint2*)(xin + (size_t)s0 * D))[sub];
            uint2 u1 = ((const uint2*)(xin + (size_t)s1 * D))[sub];
            uint2 u2 = ((const uint2*)(xin + (size_t)s2 * D))[sub];
            uint2 u3 = ((const uint2*)(xin + (size_t)s3 * D))[sub];
            float2 f0 = __half22float2(*(__half2*)&u0.x), f1 = __half22float2(*(__half2*)&u0.y);
            float2 f2 = __half22float2(*(__half2*)&u1.x), f3 = __half22float2(*(__half2*)&u1.y);
            float2 f4 = __half22float2(*(__half2*)&u2.x), f5 = __half22float2(*(__half2*)&u2.y);
            float2 f6 = __half22float2(*(__half2*)&u3.x), f7 = __half22float2(*(__half2*)&u3.y);
            ax += (f0.x + f2.x) + (f4.x + f6.x);
            ay += (f0.y + f2.y) + (f4.y + f6.y);
            az += (f1.x + f3.x) + (f5.x + f7.x);
            aw += (f1.y + f3.y) + (f5.y + f7.y);
        }
        for (; e < n; e++) {
            uint2 u = ((const uint2*)(xin + (size_t)__ldg(cs + e) * D))[sub];
            float2 f0 = __half22float2(*(__half2*)&u.x), f1 = __half22float2(*(__half2*)&u.y);
            ax += f0.x; ay += f0.y; az += f1.x; aw += f1.y;
        }
        float inn = g_innorm[node];
        uint2 o;
        *(__half2*)&o.x = __floats2half2_rn(ax * inn, ay * inn);
        *(__half2*)&o.y = __floats2half2_rn(az * inn, aw * inn);
        ((uint2*)(g_agg_h + (size_t)node * D))[sub] = o;
    }
}

// -------- batched transform via tensor cores: out = act(agg @ W + b) [* out_norm] --------
// 16 nodes per block; 4 warps, warp w computes the 16x16 output tile for cols [16w,16w+16)
template <bool RELU, bool OUTSCALE, bool HALF_OUT>
__global__ __launch_bounds__(128) void k_xform(const __half* __restrict__ Wh,
                                               const float* __restrict__ bias,
                                               void* __restrict__ outp) {
    __shared__ float sC[16 * 64];
    int w = threadIdx.x >> 5;
    int row0 = blockIdx.x * 16;

    wmma::fragment<wmma::matrix_a, 16, 16, 16, __half, wmma::row_major> a;
    wmma::fragment<wmma::matrix_b, 16, 16, 16, __half, wmma::row_major> b;
    wmma::fragment<wmma::accumulator, 16, 16, 16, float> c;
    wmma::fill_fragment(c, 0.0f);
#pragma unroll
    for (int kk = 0; kk < 4; kk++) {
        wmma::load_matrix_sync(a, g_agg_h + (size_t)row0 * D + kk * 16, D);
        wmma::load_matrix_sync(b, Wh + kk * 16 * D + w * 16, D);
        wmma::mma_sync(c, a, b, c);
    }
    wmma::store_matrix_sync(sC + w * 16, c, 64, wmma::mem_row_major);
    __syncthreads();

    int r = threadIdx.x >> 3;          // 0..15
    int cb = (threadIdx.x & 7) * 8;    // col base
    int node = row0 + r;
    float on = OUTSCALE ? g_outnorm[node] : 1.0f;
#pragma unroll
    for (int i = 0; i < 8; i++) {
        int j = cb + i;
        float v = sC[r * 64 + j] + bias[j];
        if (RELU) v = fmaxf(v, 0.0f);
        if (OUTSCALE) v *= on;
        if (HALF_OUT) ((__half*)outp)[(size_t)node * D + j] = __float2half_rn(v);
        else          ((float*)outp)[(size_t)node * D + j] = v;
    }
}

extern "C" void kernel_launch(void* const* d_in, const int* in_sizes, int n_in,
                              void* d_out, int out_size) {
    const float* emb   = (const float*)d_in[0];
    const float* gc1w  = (const float*)d_in[1];
    const float* gc2w  = (const float*)d_in[2];
    const float* gc1b  = (const float*)d_in[3];
    const float* gc2b  = (const float*)d_in[4];
    const float* p1    = (const float*)d_in[5];
    const float* p2    = (const float*)d_in[6];
    const float* W_ih  = (const float*)d_in[7];
    const float* W_hh  = (const float*)d_in[8];
    const float* b_ih  = (const float*)d_in[9];
    const float* b_hh  = (const float*)d_in[10];
    const int*   src   = (const int*)d_in[11];
    const int*   dst   = (const int*)d_in[12];

    void *p_co = nullptr, *p_ci = nullptr, *p_wh = nullptr, *p_xs = nullptr, *p_ys = nullptr;
    cudaGetSymbolAddress(&p_co, g_cnt_out);
    cudaGetSymbolAddress(&p_ci, g_cnt_in);
    cudaGetSymbolAddress(&p_wh, g_wh);
    cudaGetSymbolAddress(&p_xs, g_xs);
    cudaGetSymbolAddress(&p_ys, g_ys);
    const __half* wh1 = (const __half*)p_wh;
    const __half* wh2 = wh1 + H;

    // lazily-created side streams + fork/join events (host resources, no device mem)
    static cudaStream_t s_gru = nullptr, s_pre = nullptr;
    static cudaEvent_t  ev_fork = nullptr, ev_join = nullptr;
    static cudaEvent_t  ev_norms = nullptr, ev_scale = nullptr;
    if (s_gru == nullptr) {
        cudaStreamCreateWithFlags(&s_gru, cudaStreamNonBlocking);
        cudaStreamCreateWithFlags(&s_pre, cudaStreamNonBlocking);
        cudaEventCreateWithFlags(&ev_fork,  cudaEventDisableTiming);
        cudaEventCreateWithFlags(&ev_join,  cudaEventDisableTiming);
        cudaEventCreateWithFlags(&ev_norms, cudaEventDisableTiming);
        cudaEventCreateWithFlags(&ev_scale, cudaEventDisableTiming);
    }

    // ---- fork: GRU weight evolution on side stream (independent of graph work) ----
    cudaEventRecord(ev_fork, 0);
    cudaStreamWaitEvent(s_gru, ev_fork, 0);
    k_gru_mv<<<2 * (TH / 16), 512, 0, s_gru>>>(W_ih, W_hh, b_ih, b_hh, p1, p2, gc1w, gc2w);
    k_gru_combine<<<dim3(H / 256, 2), 256, 0, s_gru>>>(gc1w, gc2w);
    cudaEventRecord(ev_join, s_gru);

    // ---- main stream: degrees + norms ----
    cudaMemsetAsync(p_co, 0, sizeof(int) * N_NODES, 0);
    cudaMemsetAsync(p_ci, 0, sizeof(int) * N_NODES, 0);
    k_count<<<(N_EDGES / 4 + 255) / 256, 256>>>((const int4*)src, (const int4*)dst);
    k_norms<<<(N_NODES + 255) / 256, 256>>>();

    // ---- fork: input prescale (needs only out_norm) overlaps scan+scatter ----
    cudaEventRecord(ev_norms, 0);
    cudaStreamWaitEvent(s_pre, ev_norms, 0);
    k_scale_in<<<(N_NODES * 16 + 255) / 256, 256, 0, s_pre>>>(emb);
    cudaEventRecord(ev_scale, s_pre);

    // ---- main stream: scan + CSR scatter ----
    k_scan_local<<<NSCANBLK, SCAN_B>>>();
    k_scan_bsum<<<1, 128>>>();
    k_scan_add<<<(N_NODES + 255) / 256, 256>>>();
    k_csr_scatter<<<(N_EDGES / 4 + 255) / 256, 256>>>((const int4*)src, (const int4*)dst);

    // ---- join: need evolved weights + prescaled input before layer 1 ----
    cudaStreamWaitEvent(0, ev_join, 0);
    cudaStreamWaitEvent(0, ev_scale, 0);

    // ---- GCN layer 1: gather-agg then tensor-core transform (fp16 out) ----
    k_agg<<<AGG_BLOCKS, AGG_THREADS>>>((const __half*)p_xs);
    k_xform<true, true, true><<<N_NODES / 16, 128>>>(wh1, gc1b, p_ys);

    // ---- GCN layer 2: gather-agg then transform (fp32 final output) ----
    k_agg<<<AGG_BLOCKS, AGG_THREADS>>>((const __half*)p_ys);
    k_xform<false, false, false><<<N_NODES / 16, 128>>>(wh2, gc2b, d_out);
}

// round 7
// speedup vs baseline: 1.9866x; 1.1015x over previous
#include <cuda_runtime.h>
#include <cuda_fp16.h>
#include <mma.h>

#define N_NODES 100000
#define N_EDGES 3200000
#define D 64
#define H 4096
#define TH 12288  // 3*H
#define SCAN_B 1024
#define NSCANBLK ((N_NODES + SCAN_B - 1) / SCAN_B)  // 98
#define AGG_BLOCKS 592
#define AGG_THREADS 512

using namespace nvcuda;

// -------- device scratch (no allocations allowed) --------
__device__ int    g_cnt_out[N_NODES];
__device__ int    g_cnt_in[N_NODES];
__device__ float  g_outnorm[N_NODES];
__device__ float  g_innorm[N_NODES];
__device__ int    g_rowoff[N_NODES + 1];
__device__ int    g_cursor[N_NODES];
__device__ int    g_bsum[NSCANBLK];
__device__ int    g_boff[NSCANBLK];
__device__ int    g_csr[N_EDGES];               // src ids grouped by dst
__device__ float  g_gi[2][TH];
__device__ float  g_gh[2][TH];
__device__ __half g_wh[2][H];                   // evolved weights, fp16 (for wmma)
__device__ __half g_xs[(size_t)N_NODES * D];    // layer-1 input (out_norm prescaled, fp16)
__device__ __half g_ys[(size_t)N_NODES * D];    // layer-1 output / layer-2 input (fp16)
__device__ __half g_agg_h[(size_t)N_NODES * D]; // aggregated rows (in_norm applied, fp16)

// -------- degree counts (int), 4 edges per thread --------
__global__ void k_count(const int4* __restrict__ src4, const int4* __restrict__ dst4) {
    int t = blockIdx.x * blockDim.x + threadIdx.x;
    if (t >= N_EDGES / 4) return;
    int4 s = src4[t];
    int4 d = dst4[t];
    atomicAdd(&g_cnt_out[s.x], 1); atomicAdd(&g_cnt_out[s.y], 1);
    atomicAdd(&g_cnt_out[s.z], 1); atomicAdd(&g_cnt_out[s.w], 1);
    atomicAdd(&g_cnt_in[d.x], 1);  atomicAdd(&g_cnt_in[d.y], 1);
    atomicAdd(&g_cnt_in[d.z], 1);  atomicAdd(&g_cnt_in[d.w], 1);
}

// -------- exclusive scan of g_cnt_in -> g_rowoff (also emits in_norm) --------
__global__ void k_scan_local() {
    __shared__ int sh[SCAN_B];
    int tid = threadIdx.x;
    int i = blockIdx.x * SCAN_B + tid;
    int v = (i < N_NODES) ? g_cnt_in[i] : 0;
    sh[tid] = v;
    __syncthreads();
    for (int off = 1; off < SCAN_B; off <<= 1) {
        int t = 0;
        if (tid >= off) t = sh[tid - off];
        __syncthreads();
        if (tid >= off) sh[tid] += t;
        __syncthreads();
    }
    if (i < N_NODES) {
        g_rowoff[i] = sh[tid] - v;  // exclusive, block-local
        g_innorm[i] = rsqrtf(fmaxf((float)v, 1.0f));
    }
    if (tid == SCAN_B - 1) g_bsum[blockIdx.x] = sh[tid];
}

__global__ void k_scan_bsum() {
    __shared__ int sh[128];
    int tid = threadIdx.x;
    int v = (tid < NSCANBLK) ? g_bsum[tid] : 0;
    sh[tid] = v;
    __syncthreads();
    for (int off = 1; off < 128; off <<= 1) {
        int t = 0;
        if (tid >= off) t = sh[tid - off];
        __syncthreads();
        if (tid >= off) sh[tid] += t;
        __syncthreads();
    }
    if (tid < NSCANBLK) g_boff[tid] = sh[tid] - v;  // exclusive
}

__global__ void k_scan_add() {
    int i = blockIdx.x * blockDim.x + threadIdx.x;
    if (i >= N_NODES) return;
    int val = g_rowoff[i] + g_boff[i / SCAN_B];
    g_rowoff[i] = val;
    g_cursor[i] = val;
    if (i == 0) g_rowoff[N_NODES] = N_EDGES;
}

// -------- scatter edges into CSR by dst, 4 edges per thread --------
__global__ void k_csr_scatter(const int4* __restrict__ src4, const int4* __restrict__ dst4) {
    int t = blockIdx.x * blockDim.x + threadIdx.x;
    if (t >= N_EDGES / 4) return;
    int4 s = src4[t];
    int4 d = dst4[t];
    g_csr[atomicAdd(&g_cursor[d.x], 1)] = s.x;
    g_csr[atomicAdd(&g_cursor[d.y], 1)] = s.y;
    g_csr[atomicAdd(&g_cursor[d.z], 1)] = s.z;
    g_csr[atomicAdd(&g_cursor[d.w], 1)] = s.w;
}

// -------- pre-scale layer-1 input by out_norm (computed here), convert to fp16 --------
__global__ void k_scale_in(const float* __restrict__ x) {
    int t = blockIdx.x * blockDim.x + threadIdx.x;
    if (t >= N_NODES * 16) return;
    int row = t >> 4;
    float4 v = ((const float4*)x)[t];
    float s = rsqrtf(fmaxf((float)g_cnt_out[row], 1.0f));
    if ((t & 15) == 0) g_outnorm[row] = s;  // persist for xform1 epilogue
    __half2 h0 = __floats2half2_rn(v.x * s, v.y * s);
    __half2 h1 = __floats2half2_rn(v.z * s, v.w * s);
    ((__half2*)g_xs)[2 * t]     = h0;
    ((__half2*)g_xs)[2 * t + 1] = h1;
}

// -------- GRU matvec: 512 threads/block (16 rows), both cells per weight-row read --------
__global__ __launch_bounds__(512) void k_gru_mv(
        const float* __restrict__ W_ih, const float* __restrict__ W_hh,
        const float* __restrict__ b_ih, const float* __restrict__ b_hh,
        const float* __restrict__ x1, const float* __restrict__ x2,
        const float* __restrict__ h1, const float* __restrict__ h2) {
    __shared__ float4 sv1[H / 4];
    __shared__ float4 sv2[H / 4];
    const int HB = TH / 16;  // 768 blocks per matrix
    bool hh = blockIdx.x >= HB;
    const float* W  = hh ? W_hh : W_ih;
    const float* b  = hh ? b_hh : b_ih;
    const float* v1 = hh ? h1 : x1;
    const float* v2 = hh ? h2 : x2;
    float* o1 = hh ? g_gh[0] : g_gi[0];
    float* o2 = hh ? g_gh[1] : g_gi[1];

    for (int i = threadIdx.x; i < H / 4; i += blockDim.x) {
        sv1[i] = ((const float4*)v1)[i];
        sv2[i] = ((const float4*)v2)[i];
    }
    __syncthreads();

    int warp = threadIdx.x >> 5, lane = threadIdx.x & 31;
    int row = (blockIdx.x % HB) * 16 + warp;
    const float4* wr = (const float4*)(W + (size_t)row * H);
    float a1 = 0.0f, a2 = 0.0f;
#pragma unroll 8
    for (int k = lane; k < H / 4; k += 32) {
        float4 w = __ldcs(wr + k);  // streaming: no L2 reuse, keep L2 for graph data
        float4 p = sv1[k];
        float4 q = sv2[k];
        a1 += w.x * p.x + w.y * p.y + w.z * p.z + w.w * p.w;
        a2 += w.x * q.x + w.y * q.y + w.z * q.z + w.w * q.w;
    }
#pragma unroll
    for (int o = 16; o; o >>= 1) {
        a1 += __shfl_xor_sync(0xffffffffu, a1, o);
        a2 += __shfl_xor_sync(0xffffffffu, a2, o);
    }
    if (lane == 0) {
        float bb = b[row];
        o1[row] = a1 + bb;
        o2[row] = a2 + bb;
    }
}

__device__ __forceinline__ float sigm(float x) { return 1.0f / (1.0f + expf(-x)); }

// combine gates -> evolved weight, stored directly as fp16 for the wmma transform
__global__ void k_gru_combine(const float* __restrict__ gc1w, const float* __restrict__ gc2w) {
    int j = blockIdx.x * blockDim.x + threadIdx.x;
    int c = blockIdx.y;
    if (j >= H) return;
    const float* gi = g_gi[c];
    const float* gh = g_gh[c];
    const float* hv = c ? gc2w : gc1w;
    float r = sigm(gi[j] + gh[j]);
    float z = sigm(gi[H + j] + gh[H + j]);
    float n = tanhf(gi[2 * H + j] + r * gh[2 * H + j]);
    g_wh[c][j] = __float2half_rn((1.0f - z) * n + z * hv[j]);
}

// -------- persistent gather-aggregate: 8 lanes per node, 4 nodes per warp --------
// lane sub (0..7) holds features [8*sub .. 8*sub+7] as uint4 (8 halves = 16B);
// one warp-wide LDG.128 serves 4 edges (one per 8-lane group).
__global__ __launch_bounds__(AGG_THREADS) void k_agg(const __half* __restrict__ xin) {
    int lane = threadIdx.x & 31;
    int sub = lane & 7;
    int grp = lane >> 3;  // 0..3
    int gwarp = (blockIdx.x * AGG_THREADS + threadIdx.x) >> 5;
    const int nwarps = AGG_BLOCKS * (AGG_THREADS / 32);

    for (int base = gwarp * 4; base < N_NODES; base += nwarps * 4) {
        int node = base + grp;  // N_NODES % 4 == 0 -> always < N_NODES
        int beg = g_rowoff[node];
        int n = g_rowoff[node + 1] - beg;
        const int* cs = g_csr + beg;
        float a0 = 0.f, a1 = 0.f, a2 = 0.f, a3 = 0.f;
        float a4 = 0.f, a5 = 0.f, a6 = 0.f, a7 = 0.f;
        int e = 0;
        for (; e + 4 <= n; e += 4) {
            int s0 = __ldg(cs + e),     s1 = __ldg(cs + e + 1);
            int s2 = __ldg(cs + e + 2), s3 = __ldg(cs + e + 3);
            uint4 u0 = ((const uint4*)(xin + (size_t)s0 * D))[sub];
            uint4 u1 = ((const uint4*)(xin + (size_t)s1 * D))[sub];
            uint4 u2 = ((const uint4*)(xin + (size_t)s2 * D))[sub];
            uint4 u3 = ((const uint4*)(xin + (size_t)s3 * D))[sub];
            float2 f;
            f = __half22float2(*(__half2*)&u0.x); a0 += f.x; a1 += f.y;
            f = __half22float2(*(__half2*)&u0.y); a2 += f.x; a3 += f.y;
            f = __half22float2(*(__half2*)&u0.z); a4 += f.x; a5 += f.y;
            f = __half22float2(*(__half2*)&u0.w); a6 += f.x; a7 += f.y;
            f = __half22float2(*(__half2*)&u1.x); a0 += f.x; a1 += f.y;
            f = __half22float2(*(__half2*)&u1.y); a2 += f.x; a3 += f.y;
            f = __half22float2(*(__half2*)&u1.z); a4 += f.x; a5 += f.y;
            f = __half22float2(*(__half2*)&u1.w); a6 += f.x; a7 += f.y;
            f = __half22float2(*(__half2*)&u2.x); a0 += f.x; a1 += f.y;
            f = __half22float2(*(__half2*)&u2.y); a2 += f.x; a3 += f.y;
            f = __half22float2(*(__half2*)&u2.z); a4 += f.x; a5 += f.y;
            f = __half22float2(*(__half2*)&u2.w); a6 += f.x; a7 += f.y;
            f = __half22float2(*(__half2*)&u3.x); a0 += f.x; a1 += f.y;
            f = __half22float2(*(__half2*)&u3.y); a2 += f.x; a3 += f.y;
            f = __half22float2(*(__half2*)&u3.z); a4 += f.x; a5 += f.y;
            f = __half22float2(*(__half2*)&u3.w); a6 += f.x; a7 += f.y;
        }
        for (; e < n; e++) {
            uint4 u = ((const uint4*)(xin + (size_t)__ldg(cs + e) * D))[sub];
            float2 f;
            f = __half22float2(*(__half2*)&u.x); a0 += f.x; a1 += f.y;
            f = __half22float2(*(__half2*)&u.y); a2 += f.x; a3 += f.y;
            f = __half22float2(*(__half2*)&u.z); a4 += f.x; a5 += f.y;
            f = __half22float2(*(__half2*)&u.w); a6 += f.x; a7 += f.y;
        }
        float inn = g_innorm[node];
        uint4 o;
        *(__half2*)&o.x = __floats2half2_rn(a0 * inn, a1 * inn);
        *(__half2*)&o.y = __floats2half2_rn(a2 * inn, a3 * inn);
        *(__half2*)&o.z = __floats2half2_rn(a4 * inn, a5 * inn);
        *(__half2*)&o.w = __floats2half2_rn(a6 * inn, a7 * inn);
        ((uint4*)(g_agg_h + (size_t)node * D))[sub] = o;
    }
}

// -------- batched transform via tensor cores: out = act(agg @ W + b) [* out_norm] --------
// 16 nodes per block; 4 warps, warp w computes the 16x16 output tile for cols [16w,16w+16)
template <bool RELU, bool OUTSCALE, bool HALF_OUT>
__global__ __launch_bounds__(128) void k_xform(const __half* __restrict__ Wh,
                                               const float* __restrict__ bias,
                                               void* __restrict__ outp) {
    __shared__ float sC[16 * 64];
    int w = threadIdx.x >> 5;
    int row0 = blockIdx.x * 16;

    wmma::fragment<wmma::matrix_a, 16, 16, 16, __half, wmma::row_major> a;
    wmma::fragment<wmma::matrix_b, 16, 16, 16, __half, wmma::row_major> b;
    wmma::fragment<wmma::accumulator, 16, 16, 16, float> c;
    wmma::fill_fragment(c, 0.0f);
#pragma unroll
    for (int kk = 0; kk < 4; kk++) {
        wmma::load_matrix_sync(a, g_agg_h + (size_t)row0 * D + kk * 16, D);
        wmma::load_matrix_sync(b, Wh + kk * 16 * D + w * 16, D);
        wmma::mma_sync(c, a, b, c);
    }
    wmma::store_matrix_sync(sC + w * 16, c, 64, wmma::mem_row_major);
    __syncthreads();

    int r = threadIdx.x >> 3;          // 0..15
    int cb = (threadIdx.x & 7) * 8;    // col base
    int node = row0 + r;
    float on = OUTSCALE ? g_outnorm[node] : 1.0f;
#pragma unroll
    for (int i = 0; i < 8; i++) {
        int j = cb + i;
        float v = sC[r * 64 + j] + bias[j];
        if (RELU) v = fmaxf(v, 0.0f);
        if (OUTSCALE) v *= on;
        if (HALF_OUT) ((__half*)outp)[(size_t)node * D + j] = __float2half_rn(v);
        else          ((float*)outp)[(size_t)node * D + j] = v;
    }
}

extern "C" void kernel_launch(void* const* d_in, const int* in_sizes, int n_in,
                              void* d_out, int out_size) {
    const float* emb   = (const float*)d_in[0];
    const float* gc1w  = (const float*)d_in[1];
    const float* gc2w  = (const float*)d_in[2];
    const float* gc1b  = (const float*)d_in[3];
    const float* gc2b  = (const float*)d_in[4];
    const float* p1    = (const float*)d_in[5];
    const float* p2    = (const float*)d_in[6];
    const float* W_ih  = (const float*)d_in[7];
    const float* W_hh  = (const float*)d_in[8];
    const float* b_ih  = (const float*)d_in[9];
    const float* b_hh  = (const float*)d_in[10];
    const int*   src   = (const int*)d_in[11];
    const int*   dst   = (const int*)d_in[12];

    void *p_co = nullptr, *p_ci = nullptr, *p_wh = nullptr, *p_xs = nullptr, *p_ys = nullptr;
    cudaGetSymbolAddress(&p_co, g_cnt_out);
    cudaGetSymbolAddress(&p_ci, g_cnt_in);
    cudaGetSymbolAddress(&p_wh, g_wh);
    cudaGetSymbolAddress(&p_xs, g_xs);
    cudaGetSymbolAddress(&p_ys, g_ys);
    const __half* wh1 = (const __half*)p_wh;
    const __half* wh2 = wh1 + H;

    // lazily-created side streams + fork/join events (host resources, no device mem)
    static cudaStream_t s_gru = nullptr, s_pre = nullptr;
    static cudaEvent_t  ev_fork = nullptr, ev_join = nullptr;
    static cudaEvent_t  ev_cnt = nullptr, ev_scale = nullptr;
    if (s_gru == nullptr) {
        cudaStreamCreateWithFlags(&s_gru, cudaStreamNonBlocking);
        cudaStreamCreateWithFlags(&s_pre, cudaStreamNonBlocking);
        cudaEventCreateWithFlags(&ev_fork,  cudaEventDisableTiming);
        cudaEventCreateWithFlags(&ev_join,  cudaEventDisableTiming);
        cudaEventCreateWithFlags(&ev_cnt,   cudaEventDisableTiming);
        cudaEventCreateWithFlags(&ev_scale, cudaEventDisableTiming);
    }

    // ---- fork: GRU weight evolution on side stream (independent of graph work) ----
    cudaEventRecord(ev_fork, 0);
    cudaStreamWaitEvent(s_gru, ev_fork, 0);
    k_gru_mv<<<2 * (TH / 16), 512, 0, s_gru>>>(W_ih, W_hh, b_ih, b_hh, p1, p2, gc1w, gc2w);
    k_gru_combine<<<dim3(H / 256, 2), 256, 0, s_gru>>>(gc1w, gc2w);
    cudaEventRecord(ev_join, s_gru);

    // ---- main stream: degree counts ----
    cudaMemsetAsync(p_co, 0, sizeof(int) * N_NODES, 0);
    cudaMemsetAsync(p_ci, 0, sizeof(int) * N_NODES, 0);
    k_count<<<(N_EDGES / 4 + 255) / 256, 256>>>((const int4*)src, (const int4*)dst);

    // ---- fork: input prescale (derives out_norm from counts) overlaps scan+scatter ----
    cudaEventRecord(ev_cnt, 0);
    cudaStreamWaitEvent(s_pre, ev_cnt, 0);
    k_scale_in<<<(N_NODES * 16 + 255) / 256, 256, 0, s_pre>>>(emb);
    cudaEventRecord(ev_scale, s_pre);

    // ---- main stream: scan (emits in_norm) + CSR scatter ----
    k_scan_local<<<NSCANBLK, SCAN_B>>>();
    k_scan_bsum<<<1, 128>>>();
    k_scan_add<<<(N_NODES + 255) / 256, 256>>>();
    k_csr_scatter<<<(N_EDGES / 4 + 255) / 256, 256>>>((const int4*)src, (const int4*)dst);

    // ---- join: need evolved weights + prescaled input before layer 1 ----
    cudaStreamWaitEvent(0, ev_join, 0);
    cudaStreamWaitEvent(0, ev_scale, 0);

    // ---- GCN layer 1: gather-agg then tensor-core transform (fp16 out) ----
    k_agg<<<AGG_BLOCKS, AGG_THREADS>>>((const __half*)p_xs);
    k_xform<true, true, true><<<N_NODES / 16, 128>>>(wh1, gc1b, p_ys);

    // ---- GCN layer 2: gather-agg then transform (fp32 final output) ----
    k_agg<<<AGG_BLOCKS, AGG_THREADS>>>((const __half*)p_ys);
    k_xform<false, false, false><<<N_NODES / 16, 128>>>(wh2, gc2b, d_out);
}